// round 8
// baseline (speedup 1.0000x reference)
#include <cuda_runtime.h>
#include <cuda_fp16.h>
#include <cstdint>

#define NSTEPS   64
#define NTHREADS 256
#define NTILES   1024            // 262144 rows / 256 per CTA (M=32 per warp)

// SMEM: W1 [256n][64k] half, rows padded to 144B; W2 [64n][256k] half, rows 528B
//       b1 pair table (h2) 512B; y state: per-thread 64 f32, 272B pitch
#define OFF_W1 0u                // 36864
#define OFF_W2 36864u            // 33792
#define OFF_B1 70656u            // 128 h2 = 512B
#define OFF_Y  71680u            // 256*272 = 69632
#define YPITCH 272u
#define SMEM_BYTES (OFF_Y + 256u * YPITCH)   // 141312

static __device__ __forceinline__ uint32_t smem_u32(const void* p) {
    uint32_t a;
    asm("{ .reg .u64 t; cvta.to.shared.u64 t, %1; cvt.u32.u64 %0, t; }" : "=r"(a) : "l"(p));
    return a;
}
static __device__ __forceinline__ void ldsm4(uint32_t* r, uint32_t addr) {
    asm volatile("ldmatrix.sync.aligned.m8n8.x4.shared.b16 {%0,%1,%2,%3}, [%4];"
                 : "=r"(r[0]), "=r"(r[1]), "=r"(r[2]), "=r"(r[3]) : "r"(addr));
}
// f16-accum MMA: D/C packed half2, 2 regs
static __device__ __forceinline__ void mma16816h(uint32_t* d, const uint32_t* a,
                                                 uint32_t b0, uint32_t b1) {
    asm volatile(
        "mma.sync.aligned.m16n8k16.row.col.f16.f16.f16.f16 "
        "{%0,%1}, {%2,%3,%4,%5}, {%6,%7}, {%0,%1};"
        : "+r"(d[0]), "+r"(d[1])
        : "r"(a[0]), "r"(a[1]), "r"(a[2]), "r"(a[3]), "r"(b0), "r"(b1));
}
static __device__ __forceinline__ uint32_t pack_h2(float a, float b) {
    __half2 h = __floats2half2_rn(a, b);
    return *reinterpret_cast<const uint32_t*>(&h);
}
static __device__ __forceinline__ __half2 exp2h2(__half2 v) {
    uint32_t r, x = *reinterpret_cast<const uint32_t*>(&v);
    asm("ex2.approx.f16x2 %0, %1;" : "=r"(r) : "r"(x));
    return *reinterpret_cast<const __half2*>(&r);
}
// branchless h2 ELU on packed bits: max(x,0) + (exp(min(x,0)) - 1)
static __device__ __forceinline__ uint32_t elu_h2(uint32_t hu) {
    const __half2 z    = __float2half2_rn(0.0f);
    const __half2 l2e  = __float2half2_rn(1.44269504f);
    const __half2 one  = __float2half2_rn(1.0f);
    __half2 h  = *reinterpret_cast<const __half2*>(&hu);
    __half2 mn = __hmin2(h, z);
    __half2 mx = __hmax2(h, z);
    __half2 e  = exp2h2(__hmul2(mn, l2e));
    __half2 r  = __hadd2(mx, __hsub2(e, one));
    return *reinterpret_cast<const uint32_t*>(&r);
}
static __device__ __forceinline__ uint32_t hfma2_u(uint32_t a, __half2 b, uint32_t c) {
    __half2 r = __hfma2(*reinterpret_cast<const __half2*>(&a), b,
                        *reinterpret_cast<const __half2*>(&c));
    return *reinterpret_cast<const uint32_t*>(&r);
}

__global__ void __launch_bounds__(NTHREADS, 1)
node_rk4_kernel(const float* __restrict__ x, const float* __restrict__ tptr,
                const float* __restrict__ W1, const float* __restrict__ b1,
                const float* __restrict__ W2, const float* __restrict__ b2,
                float* __restrict__ out)
{
    extern __shared__ char base[];
    const int tid = threadIdx.x;
    const int wid = tid >> 5;
    const int lid = tid & 31;
    const int g   = lid >> 2;
    const int tig = lid & 3;

    // ---- stage weights (fp16, padded rows) + b1 pair table ----
    for (int i = tid; i < 256 * 64; i += NTHREADS) {
        int n = i >> 6, k = i & 63;
        *reinterpret_cast<__half*>(base + OFF_W1 + n * 144 + k * 2) = __float2half_rn(W1[i]);
    }
    for (int i = tid; i < 64 * 256; i += NTHREADS) {
        int n = i >> 8, k = i & 255;
        *reinterpret_cast<__half*>(base + OFF_W2 + n * 528 + k * 2) = __float2half_rn(W2[i]);
    }
    for (int i = tid; i < 128; i += NTHREADS) {
        int t = i >> 2, tg = i & 3;
        *reinterpret_cast<uint32_t*>(base + OFF_B1 + (uint32_t)(tg * 32 + t) * 4) =
            pack_h2(b1[8*t + 2*tg], b1[8*t + 2*tg + 1]);
    }

    const uint32_t sb = smem_u32(base);
    const uint32_t lr = lid & 7, lh = (lid >> 3) & 1, ln = (lid >> 4) & 1;
    const uint32_t w1base = sb + OFF_W1 + (lr + 8 * ln) * 144 + lh * 16;
    const uint32_t w2base = sb + OFF_W2 + (lr + 8 * ln) * 528 + lh * 16;
    float* yp = reinterpret_cast<float*>(base + OFF_Y + (uint32_t)tid * YPITCH);

    // b2 as h2 pairs for this thread's columns, tile t=0..7
    uint32_t b2h[8];
    #pragma unroll
    for (int t = 0; t < 8; t++) {
        float2 v = *reinterpret_cast<const float2*>(b2 + 8 * t + tig * 2);
        b2h[t] = pack_h2(v.x, v.y);
    }

    const float t0f = tptr[0];
    const float dt  = t0f * (1.0f / (float)NSTEPS);
    const float dt6 = dt * (1.0f / 6.0f);
    const float hdt = 0.5f * dt;
    const __half2 one_h  = __float2half2_rn(1.0f);
    const __half2 two_h  = __float2half2_rn(2.0f);
    const __half2 hdt_h  = __float2half2_rn(hdt);
    const __half2 dt_h   = __float2half2_rn(dt);
    const int rot = ((wid >> 2) & 1) * 2;   // SMSP phase stagger

    // ---- initial y: gather C-layout slices from global x ----
    const int rowbase = blockIdx.x * 256 + wid * 32 + g;
    uint32_t a1[32];   // GEMM1 A-frags (current stage input), h2
    uint32_t yh[32];   // h2 snapshot of y (stage-0 input)
    {
        float yl[64];
        #pragma unroll
        for (int rs = 0; rs < 2; rs++)
            #pragma unroll
            for (int h = 0; h < 2; h++) {
                const float2* src = reinterpret_cast<const float2*>(
                    x + (size_t)(rowbase + rs * 16 + h * 8) * 64);
                #pragma unroll
                for (int t = 0; t < 8; t++) {
                    float2 v = src[4 * t + tig];
                    yl[rs*32 + 4*t + 2*h]     = v.x;
                    yl[rs*32 + 4*t + 2*h + 1] = v.y;
                }
            }
        #pragma unroll
        for (int q = 0; q < 16; q++)
            reinterpret_cast<float4*>(yp)[q] =
                make_float4(yl[4*q], yl[4*q+1], yl[4*q+2], yl[4*q+3]);
        #pragma unroll
        for (int i = 0; i < 32; i++) {
            a1[i] = pack_h2(yl[2*i], yl[2*i+1]);
            yh[i] = a1[i];
        }
    }
    __syncthreads();

    // ---- main ODE loop ----
    #pragma unroll 1
    for (int step = 0; step < NSTEPS; ++step) {
        uint32_t acc[32];                    // RK4 accumulator (h2)
        #pragma unroll
        for (int i = 0; i < 32; i++) acc[i] = 0u;

        #pragma unroll 1
        for (int s = 0; s < 4; s++) {
            // D2 accumulators (h2), init = b2
            uint32_t d2h[32];
            #pragma unroll
            for (int rs = 0; rs < 2; rs++)
                #pragma unroll
                for (int t = 0; t < 8; t++) {
                    d2h[rs*16 + 2*t + 0] = b2h[t];
                    d2h[rs*16 + 2*t + 1] = b2h[t];
                }

            // hidden chunks of 64 (rotated order per warp-group)
            #pragma unroll 1
            for (int hc = 0; hc < 4; hc++) {
                const int ci = (hc + rot) & 3;

                // b1 pairs of this chunk
                uint32_t pv[8];
                {
                    const uint32_t boff = sb + OFF_B1 + (uint32_t)(tig * 32 + 8 * ci) * 4;
                    asm volatile("ld.shared.v4.u32 {%0,%1,%2,%3}, [%4];"
                                 : "=r"(pv[0]), "=r"(pv[1]), "=r"(pv[2]), "=r"(pv[3]) : "r"(boff));
                    asm volatile("ld.shared.v4.u32 {%0,%1,%2,%3}, [%4];"
                                 : "=r"(pv[4]), "=r"(pv[5]), "=r"(pv[6]), "=r"(pv[7]) : "r"(boff + 16));
                }

                uint32_t d1h[32];
                uint32_t a2g[8];     // transient ELU'd group (GEMM2 A-frags)

                // 4-stage pipeline over n-groups:
                //   GEMM1(g)  then  ELU(g-1) + GEMM2(kk2=g-1)
                #pragma unroll
                for (int gg = 0; gg < 4; gg++) {
                    // ldsm W1 tiles for group gg (4 x k16)
                    uint32_t bb[16];
                    #pragma unroll
                    for (int kk = 0; kk < 4; kk++)
                        ldsm4(bb + 4*kk, w1base + (uint32_t)(4*ci + gg) * 2304 + kk * 32);

                    // init d1h group gg = b1 pairs
                    d1h[4*gg+0] = pv[2*gg];   d1h[4*gg+1] = pv[2*gg];
                    d1h[4*gg+2] = pv[2*gg+1]; d1h[4*gg+3] = pv[2*gg+1];
                    d1h[16+4*gg+0] = pv[2*gg];   d1h[16+4*gg+1] = pv[2*gg];
                    d1h[16+4*gg+2] = pv[2*gg+1]; d1h[16+4*gg+3] = pv[2*gg+1];

                    // overlap work for previous group: ELU + W2 ldsm
                    uint32_t cb[16];
                    if (gg > 0) {
                        const int p = gg - 1;
                        #pragma unroll
                        for (int i = 0; i < 4; i++) {
                            a2g[i]   = elu_h2(d1h[4*p + i]);
                            a2g[4+i] = elu_h2(d1h[16 + 4*p + i]);
                        }
                        #pragma unroll
                        for (int ng2 = 0; ng2 < 4; ng2++)
                            ldsm4(cb + 4*ng2, w2base + (uint32_t)ng2 * 8448
                                              + (uint32_t)(4*ci + p) * 32);
                    }

                    // GEMM1 MMAs group gg
                    #pragma unroll
                    for (int kk = 0; kk < 4; kk++) {
                        mma16816h(d1h + 4*gg,          a1 + 4*kk,      bb[4*kk+0], bb[4*kk+1]);
                        mma16816h(d1h + 4*gg + 2,      a1 + 4*kk,      bb[4*kk+2], bb[4*kk+3]);
                        mma16816h(d1h + 16 + 4*gg,     a1 + 16 + 4*kk, bb[4*kk+0], bb[4*kk+1]);
                        mma16816h(d1h + 16 + 4*gg + 2, a1 + 16 + 4*kk, bb[4*kk+2], bb[4*kk+3]);
                    }

                    // GEMM2 MMAs kk2 = gg-1
                    if (gg > 0) {
                        #pragma unroll
                        for (int ng2 = 0; ng2 < 4; ng2++) {
                            mma16816h(d2h + 4*ng2,          a2g,     cb[4*ng2+0], cb[4*ng2+1]);
                            mma16816h(d2h + 4*ng2 + 2,      a2g,     cb[4*ng2+2], cb[4*ng2+3]);
                            mma16816h(d2h + 16 + 4*ng2,     a2g + 4, cb[4*ng2+0], cb[4*ng2+1]);
                            mma16816h(d2h + 16 + 4*ng2 + 2, a2g + 4, cb[4*ng2+2], cb[4*ng2+3]);
                        }
                    }
                }

                // pipeline tail: ELU(3) + GEMM2(kk2=3)
                {
                    uint32_t cb[16];
                    #pragma unroll
                    for (int i = 0; i < 4; i++) {
                        a2g[i]   = elu_h2(d1h[12 + i]);
                        a2g[4+i] = elu_h2(d1h[28 + i]);
                    }
                    #pragma unroll
                    for (int ng2 = 0; ng2 < 4; ng2++)
                        ldsm4(cb + 4*ng2, w2base + (uint32_t)ng2 * 8448
                                          + (uint32_t)(4*ci + 3) * 32);
                    #pragma unroll
                    for (int ng2 = 0; ng2 < 4; ng2++) {
                        mma16816h(d2h + 4*ng2,          a2g,     cb[4*ng2+0], cb[4*ng2+1]);
                        mma16816h(d2h + 4*ng2 + 2,      a2g,     cb[4*ng2+2], cb[4*ng2+3]);
                        mma16816h(d2h + 16 + 4*ng2,     a2g + 4, cb[4*ng2+0], cb[4*ng2+1]);
                        mma16816h(d2h + 16 + 4*ng2 + 2, a2g + 4, cb[4*ng2+2], cb[4*ng2+3]);
                    }
                }
            }

            // ---- RK4 stage update (all h2) ----
            const __half2 wh = (s == 1 || s == 2) ? two_h : one_h;
            #pragma unroll
            for (int i = 0; i < 32; i++) acc[i] = hfma2_u(d2h[i], wh, acc[i]);

            if (s < 3) {
                const __half2 cnh = (s < 2) ? hdt_h : dt_h;
                #pragma unroll
                for (int i = 0; i < 32; i++) a1[i] = hfma2_u(d2h[i], cnh, yh[i]);
            } else {
                float yl[64];
                #pragma unroll
                for (int q = 0; q < 16; q++) {
                    float4 v = reinterpret_cast<const float4*>(yp)[q];
                    yl[4*q] = v.x; yl[4*q+1] = v.y; yl[4*q+2] = v.z; yl[4*q+3] = v.w;
                }
                #pragma unroll
                for (int i = 0; i < 32; i++) {
                    float2 af = __half22float2(*reinterpret_cast<const __half2*>(&acc[i]));
                    yl[2*i]     += dt6 * af.x;
                    yl[2*i + 1] += dt6 * af.y;
                }
                #pragma unroll
                for (int q = 0; q < 16; q++)
                    reinterpret_cast<float4*>(yp)[q] =
                        make_float4(yl[4*q], yl[4*q+1], yl[4*q+2], yl[4*q+3]);
                #pragma unroll
                for (int i = 0; i < 32; i++) {
                    a1[i] = pack_h2(yl[2*i], yl[2*i+1]);
                    yh[i] = a1[i];
                }
            }
        }
    }

    // ---- output ----
    {
        float yl[64];
        #pragma unroll
        for (int q = 0; q < 16; q++) {
            float4 v = reinterpret_cast<const float4*>(yp)[q];
            yl[4*q] = v.x; yl[4*q+1] = v.y; yl[4*q+2] = v.z; yl[4*q+3] = v.w;
        }
        #pragma unroll
        for (int rs = 0; rs < 2; rs++)
            #pragma unroll
            for (int h = 0; h < 2; h++) {
                float2* dst = reinterpret_cast<float2*>(
                    out + (size_t)(rowbase + rs * 16 + h * 8) * 64);
                #pragma unroll
                for (int t = 0; t < 8; t++)
                    dst[4 * t + tig] = make_float2(yl[rs*32 + 4*t + 2*h],
                                                   yl[rs*32 + 4*t + 2*h + 1]);
            }
    }
}

extern "C" void kernel_launch(void* const* d_in, const int* in_sizes, int n_in,
                              void* d_out, int out_size) {
    const float* x  = (const float*)d_in[0];
    const float* t  = (const float*)d_in[1];
    const float* W1 = (const float*)d_in[2];
    const float* b1 = (const float*)d_in[3];
    const float* W2 = (const float*)d_in[4];
    const float* b2 = (const float*)d_in[5];
    float* out = (float*)d_out;

    cudaFuncSetAttribute(node_rk4_kernel,
                         cudaFuncAttributeMaxDynamicSharedMemorySize, SMEM_BYTES);
    node_rk4_kernel<<<NTILES, NTHREADS, SMEM_BYTES>>>(x, t, W1, b1, W2, b2, out);
}

// round 9
// speedup vs baseline: 1.0025x; 1.0025x over previous
#include <cuda_runtime.h>
#include <cuda_fp16.h>
#include <cstdint>

#define NSTEPS   64
#define NTHREADS 256
#define NTILES   1024            // 262144 rows / 256 per CTA (M=32 per warp)

// SMEM: W1 [256n][64k] half, rows padded to 144B; W2 [64n][256k] half, rows 528B
//       b1 pair table (h2) 512B; y state: per-thread 64 f32, 272B pitch
#define OFF_W1 0u                // 36864
#define OFF_W2 36864u            // 33792
#define OFF_B1 70656u            // 128 h2 = 512B
#define OFF_Y  71680u            // 256*272 = 69632
#define YPITCH 272u
#define SMEM_BYTES (OFF_Y + 256u * YPITCH)   // 141312

static __device__ __forceinline__ uint32_t smem_u32(const void* p) {
    uint32_t a;
    asm("{ .reg .u64 t; cvta.to.shared.u64 t, %1; cvt.u32.u64 %0, t; }" : "=r"(a) : "l"(p));
    return a;
}
static __device__ __forceinline__ void ldsm4(uint32_t* r, uint32_t addr) {
    asm volatile("ldmatrix.sync.aligned.m8n8.x4.shared.b16 {%0,%1,%2,%3}, [%4];"
                 : "=r"(r[0]), "=r"(r[1]), "=r"(r[2]), "=r"(r[3]) : "r"(addr));
}
// f16-accum MMA: D/C packed half2, 2 regs
static __device__ __forceinline__ void mma16816h(uint32_t* d, const uint32_t* a,
                                                 uint32_t b0, uint32_t b1) {
    asm volatile(
        "mma.sync.aligned.m16n8k16.row.col.f16.f16.f16.f16 "
        "{%0,%1}, {%2,%3,%4,%5}, {%6,%7}, {%0,%1};"
        : "+r"(d[0]), "+r"(d[1])
        : "r"(a[0]), "r"(a[1]), "r"(a[2]), "r"(a[3]), "r"(b0), "r"(b1));
}
static __device__ __forceinline__ uint32_t pack_h2(float a, float b) {
    __half2 h = __floats2half2_rn(a, b);
    return *reinterpret_cast<const uint32_t*>(&h);
}
static __device__ __forceinline__ __half2 exp2h2(__half2 v) {
    uint32_t r, x = *reinterpret_cast<const uint32_t*>(&v);
    asm("ex2.approx.f16x2 %0, %1;" : "=r"(r) : "r"(x));
    return *reinterpret_cast<const __half2*>(&r);
}
// branchless h2 ELU on packed bits: max(x,0) + (exp(min(x,0)) - 1)
static __device__ __forceinline__ uint32_t elu_h2(uint32_t hu) {
    const __half2 z    = __float2half2_rn(0.0f);
    const __half2 l2e  = __float2half2_rn(1.44269504f);
    const __half2 one  = __float2half2_rn(1.0f);
    __half2 h  = *reinterpret_cast<const __half2*>(&hu);
    __half2 mn = __hmin2(h, z);
    __half2 mx = __hmax2(h, z);
    __half2 e  = exp2h2(__hmul2(mn, l2e));
    __half2 r  = __hadd2(mx, __hsub2(e, one));
    return *reinterpret_cast<const uint32_t*>(&r);
}
static __device__ __forceinline__ uint32_t hfma2_u(uint32_t a, __half2 b, uint32_t c) {
    __half2 r = __hfma2(*reinterpret_cast<const __half2*>(&a), b,
                        *reinterpret_cast<const __half2*>(&c));
    return *reinterpret_cast<const uint32_t*>(&r);
}

__global__ void __launch_bounds__(NTHREADS, 1)
node_rk4_kernel(const float* __restrict__ x, const float* __restrict__ tptr,
                const float* __restrict__ W1, const float* __restrict__ b1,
                const float* __restrict__ W2, const float* __restrict__ b2,
                float* __restrict__ out)
{
    extern __shared__ char base[];
    const int tid = threadIdx.x;
    const int wid = tid >> 5;
    const int lid = tid & 31;
    const int g   = lid >> 2;
    const int tig = lid & 3;

    // ---- stage weights (fp16, padded rows) + b1 pair table ----
    for (int i = tid; i < 256 * 64; i += NTHREADS) {
        int n = i >> 6, k = i & 63;
        *reinterpret_cast<__half*>(base + OFF_W1 + n * 144 + k * 2) = __float2half_rn(W1[i]);
    }
    for (int i = tid; i < 64 * 256; i += NTHREADS) {
        int n = i >> 8, k = i & 255;
        *reinterpret_cast<__half*>(base + OFF_W2 + n * 528 + k * 2) = __float2half_rn(W2[i]);
    }
    for (int i = tid; i < 128; i += NTHREADS) {
        int t = i >> 2, tg = i & 3;
        *reinterpret_cast<uint32_t*>(base + OFF_B1 + (uint32_t)(tg * 32 + t) * 4) =
            pack_h2(b1[8*t + 2*tg], b1[8*t + 2*tg + 1]);
    }

    const uint32_t sb = smem_u32(base);
    const uint32_t lr = lid & 7, lh = (lid >> 3) & 1, ln = (lid >> 4) & 1;
    const uint32_t w1base = sb + OFF_W1 + (lr + 8 * ln) * 144 + lh * 16;
    const uint32_t w2base = sb + OFF_W2 + (lr + 8 * ln) * 528 + lh * 16;
    float* yp = reinterpret_cast<float*>(base + OFF_Y + (uint32_t)tid * YPITCH);

    // b2 as h2 pairs for this thread's columns, tile t=0..7
    uint32_t b2h[8];
    #pragma unroll
    for (int t = 0; t < 8; t++) {
        float2 v = *reinterpret_cast<const float2*>(b2 + 8 * t + tig * 2);
        b2h[t] = pack_h2(v.x, v.y);
    }

    const float t0f = tptr[0];
    const float dt  = t0f * (1.0f / (float)NSTEPS);
    const float dt6 = dt * (1.0f / 6.0f);
    const float hdt = 0.5f * dt;
    const __half2 one_h  = __float2half2_rn(1.0f);
    const __half2 two_h  = __float2half2_rn(2.0f);
    const __half2 hdt_h  = __float2half2_rn(hdt);
    const __half2 dt_h   = __float2half2_rn(dt);
    const int rot = ((wid >> 2) & 1) * 2;   // SMSP phase stagger

    // ---- initial y: gather C-layout slices from global x ----
    const int rowbase = blockIdx.x * 256 + wid * 32 + g;
    uint32_t a1[32];   // GEMM1 A-frags (current stage input), h2
    uint32_t yh[32];   // h2 snapshot of y (stage-0 input)
    {
        float yl[64];
        #pragma unroll
        for (int rs = 0; rs < 2; rs++)
            #pragma unroll
            for (int h = 0; h < 2; h++) {
                const float2* src = reinterpret_cast<const float2*>(
                    x + (size_t)(rowbase + rs * 16 + h * 8) * 64);
                #pragma unroll
                for (int t = 0; t < 8; t++) {
                    float2 v = src[4 * t + tig];
                    yl[rs*32 + 4*t + 2*h]     = v.x;
                    yl[rs*32 + 4*t + 2*h + 1] = v.y;
                }
            }
        #pragma unroll
        for (int q = 0; q < 16; q++)
            reinterpret_cast<float4*>(yp)[q] =
                make_float4(yl[4*q], yl[4*q+1], yl[4*q+2], yl[4*q+3]);
        #pragma unroll
        for (int i = 0; i < 32; i++) {
            a1[i] = pack_h2(yl[2*i], yl[2*i+1]);
            yh[i] = a1[i];
        }
    }
    __syncthreads();

    // ---- persistent one-chunk-ahead prefetch state ----
    uint32_t nbb[4];   // next chunk's first W1 k-tile
    uint32_t npv[8];   // next chunk's b1 pairs
    {
        const int ci0 = rot;   // first chunk of the first stage
        ldsm4(nbb, w1base + (uint32_t)(4 * ci0) * 2304);
        const uint32_t boff = sb + OFF_B1 + (uint32_t)(tig * 32 + 8 * ci0) * 4;
        asm volatile("ld.shared.v4.u32 {%0,%1,%2,%3}, [%4];"
                     : "=r"(npv[0]), "=r"(npv[1]), "=r"(npv[2]), "=r"(npv[3]) : "r"(boff));
        asm volatile("ld.shared.v4.u32 {%0,%1,%2,%3}, [%4];"
                     : "=r"(npv[4]), "=r"(npv[5]), "=r"(npv[6]), "=r"(npv[7]) : "r"(boff + 16));
    }

    // ---- main ODE loop ----
    #pragma unroll 1
    for (int step = 0; step < NSTEPS; ++step) {
        uint32_t acc[32];                    // RK4 accumulator (h2)
        #pragma unroll
        for (int i = 0; i < 32; i++) acc[i] = 0u;

        #pragma unroll 1
        for (int s = 0; s < 4; s++) {
            // D2 accumulators (h2), init = b2
            uint32_t d2h[32];
            #pragma unroll
            for (int rs = 0; rs < 2; rs++)
                #pragma unroll
                for (int t = 0; t < 8; t++) {
                    d2h[rs*16 + 2*t + 0] = b2h[t];
                    d2h[rs*16 + 2*t + 1] = b2h[t];
                }

            // hidden chunks of 64 (rotated order per warp-group)
            #pragma unroll 1
            for (int hc = 0; hc < 4; hc++) {
                const int ci = (hc + rot) & 3;

                // consume prefetched b1 pairs + first W1 tile
                uint32_t pv[8];
                #pragma unroll
                for (int i = 0; i < 8; i++) pv[i] = npv[i];
                uint32_t bbX[4], bbY[4];
                #pragma unroll
                for (int i = 0; i < 4; i++) bbX[i] = nbb[i];

                // d1h init = b1 pairs of this chunk (h2 accumulators)
                uint32_t d1h[32];
                #pragma unroll
                for (int rs = 0; rs < 2; rs++)
                    #pragma unroll
                    for (int lt = 0; lt < 8; lt++) {
                        d1h[rs*16 + 2*lt + 0] = pv[lt];
                        d1h[rs*16 + 2*lt + 1] = pv[lt];
                    }

                // GEMM1 chunk (f16 accum), ldsm double-buffered (tile0 prefetched)
                #pragma unroll
                for (int j = 0; j < 16; j++) {
                    const int ngl = j >> 2, kk = j & 3;
                    uint32_t* cur = (j & 1) ? bbY : bbX;
                    uint32_t* nxt = (j & 1) ? bbX : bbY;
                    if (j < 15) {
                        const int jn = j + 1;
                        ldsm4(nxt, w1base + (uint32_t)(4*ci + (jn >> 2)) * 2304 + (jn & 3) * 32);
                    }
                    mma16816h(d1h + 4*ngl,          a1 + 4*kk,      cur[0], cur[1]);
                    mma16816h(d1h + 4*ngl + 2,      a1 + 4*kk,      cur[2], cur[3]);
                    mma16816h(d1h + 16 + 4*ngl,     a1 + 16 + 4*kk, cur[0], cur[1]);
                    mma16816h(d1h + 16 + 4*ngl + 2, a1 + 16 + 4*kk, cur[2], cur[3]);
                }

                // issue NEXT chunk's prefetch now; latency drains under ELU + GEMM2.
                // (ci_next wraps across stage/step boundaries back to rot.)
                {
                    const int cn = (hc + 1 + rot) & 3;
                    ldsm4(nbb, w1base + (uint32_t)(4 * cn) * 2304);
                    const uint32_t boffn = sb + OFF_B1 + (uint32_t)(tig * 32 + 8 * cn) * 4;
                    asm volatile("ld.shared.v4.u32 {%0,%1,%2,%3}, [%4];"
                                 : "=r"(npv[0]), "=r"(npv[1]), "=r"(npv[2]), "=r"(npv[3]) : "r"(boffn));
                    asm volatile("ld.shared.v4.u32 {%0,%1,%2,%3}, [%4];"
                                 : "=r"(npv[4]), "=r"(npv[5]), "=r"(npv[6]), "=r"(npv[7]) : "r"(boffn + 16));
                }

                // prefetch first GEMM2 B-tile BEFORE the ELU block
                uint32_t cbX[4], cbY[4];
                ldsm4(cbX, w2base + (uint32_t)(4*ci) * 32);

                // ELU: elementwise h2 (output already in GEMM2 A-frag layout)
                uint32_t a2c[32];
                #pragma unroll
                for (int i = 0; i < 32; i++) a2c[i] = elu_h2(d1h[i]);

                // GEMM2 partial over this k64 chunk (f16 accum), double-buffered
                #pragma unroll
                for (int j = 0; j < 16; j++) {
                    const int ng2 = j >> 2, kk2 = j & 3;
                    uint32_t* cur = (j & 1) ? cbY : cbX;
                    uint32_t* nxt = (j & 1) ? cbX : cbY;
                    if (j < 15) {
                        const int jn = j + 1;
                        ldsm4(nxt, w2base + (uint32_t)(jn >> 2) * 8448
                                          + (uint32_t)(4*ci + (jn & 3)) * 32);
                    }
                    mma16816h(d2h + 4*ng2,          a2c + 4*kk2,      cur[0], cur[1]);
                    mma16816h(d2h + 4*ng2 + 2,      a2c + 4*kk2,      cur[2], cur[3]);
                    mma16816h(d2h + 16 + 4*ng2,     a2c + 16 + 4*kk2, cur[0], cur[1]);
                    mma16816h(d2h + 16 + 4*ng2 + 2, a2c + 16 + 4*kk2, cur[2], cur[3]);
                }
            }

            // ---- RK4 stage update (all h2); a1 (gating value) first ----
            if (s < 3) {
                const __half2 cnh = (s < 2) ? hdt_h : dt_h;
                #pragma unroll
                for (int i = 0; i < 32; i++) a1[i] = hfma2_u(d2h[i], cnh, yh[i]);
                const __half2 wh = (s == 1 || s == 2) ? two_h : one_h;
                #pragma unroll
                for (int i = 0; i < 32; i++) acc[i] = hfma2_u(d2h[i], wh, acc[i]);
            } else {
                #pragma unroll
                for (int i = 0; i < 32; i++) acc[i] = hfma2_u(d2h[i], one_h, acc[i]);
                float yl[64];
                #pragma unroll
                for (int q = 0; q < 16; q++) {
                    float4 v = reinterpret_cast<const float4*>(yp)[q];
                    yl[4*q] = v.x; yl[4*q+1] = v.y; yl[4*q+2] = v.z; yl[4*q+3] = v.w;
                }
                #pragma unroll
                for (int i = 0; i < 32; i++) {
                    float2 af = __half22float2(*reinterpret_cast<const __half2*>(&acc[i]));
                    yl[2*i]     += dt6 * af.x;
                    yl[2*i + 1] += dt6 * af.y;
                }
                #pragma unroll
                for (int q = 0; q < 16; q++)
                    reinterpret_cast<float4*>(yp)[q] =
                        make_float4(yl[4*q], yl[4*q+1], yl[4*q+2], yl[4*q+3]);
                #pragma unroll
                for (int i = 0; i < 32; i++) {
                    a1[i] = pack_h2(yl[2*i], yl[2*i+1]);
                    yh[i] = a1[i];
                }
            }
        }
    }

    // ---- output ----
    {
        float yl[64];
        #pragma unroll
        for (int q = 0; q < 16; q++) {
            float4 v = reinterpret_cast<const float4*>(yp)[q];
            yl[4*q] = v.x; yl[4*q+1] = v.y; yl[4*q+2] = v.z; yl[4*q+3] = v.w;
        }
        #pragma unroll
        for (int rs = 0; rs < 2; rs++)
            #pragma unroll
            for (int h = 0; h < 2; h++) {
                float2* dst = reinterpret_cast<float2*>(
                    out + (size_t)(rowbase + rs * 16 + h * 8) * 64);
                #pragma unroll
                for (int t = 0; t < 8; t++)
                    dst[4 * t + tig] = make_float2(yl[rs*32 + 4*t + 2*h],
                                                   yl[rs*32 + 4*t + 2*h + 1]);
            }
    }
}

extern "C" void kernel_launch(void* const* d_in, const int* in_sizes, int n_in,
                              void* d_out, int out_size) {
    const float* x  = (const float*)d_in[0];
    const float* t  = (const float*)d_in[1];
    const float* W1 = (const float*)d_in[2];
    const float* b1 = (const float*)d_in[3];
    const float* W2 = (const float*)d_in[4];
    const float* b2 = (const float*)d_in[5];
    float* out = (float*)d_out;

    cudaFuncSetAttribute(node_rk4_kernel,
                         cudaFuncAttributeMaxDynamicSharedMemorySize, SMEM_BYTES);
    node_rk4_kernel<<<NTILES, NTHREADS, SMEM_BYTES>>>(x, t, W1, b1, W2, b2, out);
}

// round 10
// speedup vs baseline: 1.0125x; 1.0099x over previous
#include <cuda_runtime.h>
#include <cuda_fp16.h>
#include <cstdint>

#define NSTEPS   64
#define NTHREADS 256
#define NTILES   1024            // 262144 rows / 256 per CTA (M=32 per warp)

// SMEM: W1 [256n][64k] half, rows padded to 144B; W2 [64n][256k] half, rows 528B
//       b1 pair table (h2) 512B; y state: per-thread 64 f32, 272B pitch
#define OFF_W1 0u                // 36864
#define OFF_W2 36864u            // 33792
#define OFF_B1 70656u            // 128 h2 = 512B
#define OFF_Y  71680u            // 256*272 = 69632
#define YPITCH 272u
#define SMEM_BYTES (OFF_Y + 256u * YPITCH)   // 141312

static __device__ __forceinline__ uint32_t smem_u32(const void* p) {
    uint32_t a;
    asm("{ .reg .u64 t; cvta.to.shared.u64 t, %1; cvt.u32.u64 %0, t; }" : "=r"(a) : "l"(p));
    return a;
}
static __device__ __forceinline__ void ldsm4(uint32_t* r, uint32_t addr) {
    asm volatile("ldmatrix.sync.aligned.m8n8.x4.shared.b16 {%0,%1,%2,%3}, [%4];"
                 : "=r"(r[0]), "=r"(r[1]), "=r"(r[2]), "=r"(r[3]) : "r"(addr));
}
// f16-accum MMA: D/C packed half2, 2 regs
static __device__ __forceinline__ void mma16816h(uint32_t* d, const uint32_t* a,
                                                 uint32_t b0, uint32_t b1) {
    asm volatile(
        "mma.sync.aligned.m16n8k16.row.col.f16.f16.f16.f16 "
        "{%0,%1}, {%2,%3,%4,%5}, {%6,%7}, {%0,%1};"
        : "+r"(d[0]), "+r"(d[1])
        : "r"(a[0]), "r"(a[1]), "r"(a[2]), "r"(a[3]), "r"(b0), "r"(b1));
}
static __device__ __forceinline__ uint32_t pack_h2(float a, float b) {
    __half2 h = __floats2half2_rn(a, b);
    return *reinterpret_cast<const uint32_t*>(&h);
}
static __device__ __forceinline__ __half2 exp2h2(__half2 v) {
    uint32_t r, x = *reinterpret_cast<const uint32_t*>(&v);
    asm("ex2.approx.f16x2 %0, %1;" : "=r"(r) : "r"(x));
    return *reinterpret_cast<const __half2*>(&r);
}
// branchless h2 ELU on packed bits: max(x,0) + (exp(min(x,0)) - 1)
static __device__ __forceinline__ uint32_t elu_h2(uint32_t hu) {
    const __half2 z    = __float2half2_rn(0.0f);
    const __half2 l2e  = __float2half2_rn(1.44269504f);
    const __half2 one  = __float2half2_rn(1.0f);
    __half2 h  = *reinterpret_cast<const __half2*>(&hu);
    __half2 mn = __hmin2(h, z);
    __half2 mx = __hmax2(h, z);
    __half2 e  = exp2h2(__hmul2(mn, l2e));
    __half2 r  = __hadd2(mx, __hsub2(e, one));
    return *reinterpret_cast<const uint32_t*>(&r);
}
static __device__ __forceinline__ uint32_t hfma2_u(uint32_t a, __half2 b, uint32_t c) {
    __half2 r = __hfma2(*reinterpret_cast<const __half2*>(&a), b,
                        *reinterpret_cast<const __half2*>(&c));
    return *reinterpret_cast<const uint32_t*>(&r);
}

__global__ void __launch_bounds__(NTHREADS, 1)
node_rk4_kernel(const float* __restrict__ x, const float* __restrict__ tptr,
                const float* __restrict__ W1, const float* __restrict__ b1,
                const float* __restrict__ W2, const float* __restrict__ b2,
                float* __restrict__ out)
{
    extern __shared__ char base[];
    const int tid = threadIdx.x;
    const int wid = tid >> 5;
    const int lid = tid & 31;
    const int g   = lid >> 2;
    const int tig = lid & 3;

    // ---- stage weights (fp16, padded rows) + b1 pair table ----
    for (int i = tid; i < 256 * 64; i += NTHREADS) {
        int n = i >> 6, k = i & 63;
        *reinterpret_cast<__half*>(base + OFF_W1 + n * 144 + k * 2) = __float2half_rn(W1[i]);
    }
    for (int i = tid; i < 64 * 256; i += NTHREADS) {
        int n = i >> 8, k = i & 255;
        *reinterpret_cast<__half*>(base + OFF_W2 + n * 528 + k * 2) = __float2half_rn(W2[i]);
    }
    for (int i = tid; i < 128; i += NTHREADS) {
        int t = i >> 2, tg = i & 3;
        *reinterpret_cast<uint32_t*>(base + OFF_B1 + (uint32_t)(tg * 32 + t) * 4) =
            pack_h2(b1[8*t + 2*tg], b1[8*t + 2*tg + 1]);
    }

    const uint32_t sb = smem_u32(base);
    const uint32_t lr = lid & 7, lh = (lid >> 3) & 1, ln = (lid >> 4) & 1;
    const uint32_t w1base = sb + OFF_W1 + (lr + 8 * ln) * 144 + lh * 16;
    const uint32_t w2base = sb + OFF_W2 + (lr + 8 * ln) * 528 + lh * 16;
    float* yp = reinterpret_cast<float*>(base + OFF_Y + (uint32_t)tid * YPITCH);

    // b2 as h2 pairs for this thread's columns, tile t=0..7
    uint32_t b2h[8];
    #pragma unroll
    for (int t = 0; t < 8; t++) {
        float2 v = *reinterpret_cast<const float2*>(b2 + 8 * t + tig * 2);
        b2h[t] = pack_h2(v.x, v.y);
    }

    const float t0f = tptr[0];
    const float dt  = t0f * (1.0f / (float)NSTEPS);
    const float dt6 = dt * (1.0f / 6.0f);
    const float hdt = 0.5f * dt;
    const __half2 one_h  = __float2half2_rn(1.0f);
    const __half2 two_h  = __float2half2_rn(2.0f);
    const __half2 hdt_h  = __float2half2_rn(hdt);
    const __half2 dt_h   = __float2half2_rn(dt);
    const int rot = ((wid >> 2) & 1) * 2;   // SMSP phase stagger

    // ---- initial y: gather C-layout slices from global x ----
    const int rowbase = blockIdx.x * 256 + wid * 32 + g;
    uint32_t a1[32];   // GEMM1 A-frags (current stage input), h2
    uint32_t yh[32];   // h2 snapshot of y (stage-0 input)
    {
        float yl[64];
        #pragma unroll
        for (int rs = 0; rs < 2; rs++)
            #pragma unroll
            for (int h = 0; h < 2; h++) {
                const float2* src = reinterpret_cast<const float2*>(
                    x + (size_t)(rowbase + rs * 16 + h * 8) * 64);
                #pragma unroll
                for (int t = 0; t < 8; t++) {
                    float2 v = src[4 * t + tig];
                    yl[rs*32 + 4*t + 2*h]     = v.x;
                    yl[rs*32 + 4*t + 2*h + 1] = v.y;
                }
            }
        #pragma unroll
        for (int q = 0; q < 16; q++)
            reinterpret_cast<float4*>(yp)[q] =
                make_float4(yl[4*q], yl[4*q+1], yl[4*q+2], yl[4*q+3]);
        #pragma unroll
        for (int i = 0; i < 32; i++) {
            a1[i] = pack_h2(yl[2*i], yl[2*i+1]);
            yh[i] = a1[i];
        }
    }
    __syncthreads();

    // ---- main ODE loop ----
    #pragma unroll 1
    for (int step = 0; step < NSTEPS; ++step) {
        uint32_t acc[32];                    // RK4 accumulator (h2)
        #pragma unroll
        for (int i = 0; i < 32; i++) acc[i] = 0u;

        #pragma unroll 1
        for (int s = 0; s < 4; s++) {
            // D2 accumulators (h2), init = b2
            uint32_t d2h[32];
            #pragma unroll
            for (int rs = 0; rs < 2; rs++)
                #pragma unroll
                for (int t = 0; t < 8; t++) {
                    d2h[rs*16 + 2*t + 0] = b2h[t];
                    d2h[rs*16 + 2*t + 1] = b2h[t];
                }

            // hidden chunks of 64 (rotated order per warp-group)
            #pragma unroll 1
            for (int hc = 0; hc < 4; hc++) {
                const int ci = (hc + rot) & 3;

                // prefetch first GEMM1 B-tile of this chunk (ngl=0, kk=0)
                uint32_t bbX[4], bbY[4];
                ldsm4(bbX, w1base + (uint32_t)(4*ci) * 2304);

                // d1h init = b1 pairs of this chunk (h2 accumulators)
                uint32_t d1h[32];
                {
                    const uint32_t boff = sb + OFF_B1 + (uint32_t)(tig * 32 + 8 * ci) * 4;
                    uint4 pA, pB;
                    asm volatile("ld.shared.v4.u32 {%0,%1,%2,%3}, [%4];"
                                 : "=r"(pA.x), "=r"(pA.y), "=r"(pA.z), "=r"(pA.w) : "r"(boff));
                    asm volatile("ld.shared.v4.u32 {%0,%1,%2,%3}, [%4];"
                                 : "=r"(pB.x), "=r"(pB.y), "=r"(pB.z), "=r"(pB.w) : "r"(boff + 16));
                    uint32_t pv[8] = {pA.x, pA.y, pA.z, pA.w, pB.x, pB.y, pB.z, pB.w};
                    #pragma unroll
                    for (int rs = 0; rs < 2; rs++)
                        #pragma unroll
                        for (int lt = 0; lt < 8; lt++) {
                            d1h[rs*16 + 2*lt + 0] = pv[lt];
                            d1h[rs*16 + 2*lt + 1] = pv[lt];
                        }
                }

                // GEMM1 chunk (f16 accum), ldsm double-buffered.
                // Loop order: kk OUTER (j>>2), ngl INNER (j&3) -> same-accumulator
                // dependency distance = 16 MMAs instead of 4.
                #pragma unroll
                for (int j = 0; j < 16; j++) {
                    const int ngl = j & 3, kk = j >> 2;
                    uint32_t* cur = (j & 1) ? bbY : bbX;
                    uint32_t* nxt = (j & 1) ? bbX : bbY;
                    if (j < 15) {
                        const int jn = j + 1;
                        ldsm4(nxt, w1base + (uint32_t)(4*ci + (jn & 3)) * 2304 + (jn >> 2) * 32);
                    }
                    mma16816h(d1h + 4*ngl,          a1 + 4*kk,      cur[0], cur[1]);
                    mma16816h(d1h + 4*ngl + 2,      a1 + 4*kk,      cur[2], cur[3]);
                    mma16816h(d1h + 16 + 4*ngl,     a1 + 16 + 4*kk, cur[0], cur[1]);
                    mma16816h(d1h + 16 + 4*ngl + 2, a1 + 16 + 4*kk, cur[2], cur[3]);
                }

                // prefetch first GEMM2 B-tile BEFORE the ELU block (ng2=0, kk2=0)
                uint32_t cbX[4], cbY[4];
                ldsm4(cbX, w2base + (uint32_t)(4*ci) * 32);

                // ELU: elementwise h2 (output already in GEMM2 A-frag layout)
                uint32_t a2c[32];
                #pragma unroll
                for (int i = 0; i < 32; i++) a2c[i] = elu_h2(d1h[i]);

                // GEMM2 partial over this k64 chunk (f16 accum), double-buffered.
                // Loop order: kk2 OUTER (j>>2), ng2 INNER (j&3).
                #pragma unroll
                for (int j = 0; j < 16; j++) {
                    const int ng2 = j & 3, kk2 = j >> 2;
                    uint32_t* cur = (j & 1) ? cbY : cbX;
                    uint32_t* nxt = (j & 1) ? cbX : cbY;
                    if (j < 15) {
                        const int jn = j + 1;
                        ldsm4(nxt, w2base + (uint32_t)(jn & 3) * 8448
                                          + (uint32_t)(4*ci + (jn >> 2)) * 32);
                    }
                    mma16816h(d2h + 4*ng2,          a2c + 4*kk2,      cur[0], cur[1]);
                    mma16816h(d2h + 4*ng2 + 2,      a2c + 4*kk2,      cur[2], cur[3]);
                    mma16816h(d2h + 16 + 4*ng2,     a2c + 16 + 4*kk2, cur[0], cur[1]);
                    mma16816h(d2h + 16 + 4*ng2 + 2, a2c + 16 + 4*kk2, cur[2], cur[3]);
                }
            }

            // ---- RK4 stage update (all h2); a1 (gating value) first ----
            if (s < 3) {
                const __half2 cnh = (s < 2) ? hdt_h : dt_h;
                #pragma unroll
                for (int i = 0; i < 32; i++) a1[i] = hfma2_u(d2h[i], cnh, yh[i]);
                const __half2 wh = (s == 1 || s == 2) ? two_h : one_h;
                #pragma unroll
                for (int i = 0; i < 32; i++) acc[i] = hfma2_u(d2h[i], wh, acc[i]);
            } else {
                #pragma unroll
                for (int i = 0; i < 32; i++) acc[i] = hfma2_u(d2h[i], one_h, acc[i]);
                float yl[64];
                #pragma unroll
                for (int q = 0; q < 16; q++) {
                    float4 v = reinterpret_cast<const float4*>(yp)[q];
                    yl[4*q] = v.x; yl[4*q+1] = v.y; yl[4*q+2] = v.z; yl[4*q+3] = v.w;
                }
                #pragma unroll
                for (int i = 0; i < 32; i++) {
                    float2 af = __half22float2(*reinterpret_cast<const __half2*>(&acc[i]));
                    yl[2*i]     += dt6 * af.x;
                    yl[2*i + 1] += dt6 * af.y;
                }
                #pragma unroll
                for (int q = 0; q < 16; q++)
                    reinterpret_cast<float4*>(yp)[q] =
                        make_float4(yl[4*q], yl[4*q+1], yl[4*q+2], yl[4*q+3]);
                #pragma unroll
                for (int i = 0; i < 32; i++) {
                    a1[i] = pack_h2(yl[2*i], yl[2*i+1]);
                    yh[i] = a1[i];
                }
            }
        }
    }

    // ---- output ----
    {
        float yl[64];
        #pragma unroll
        for (int q = 0; q < 16; q++) {
            float4 v = reinterpret_cast<const float4*>(yp)[q];
            yl[4*q] = v.x; yl[4*q+1] = v.y; yl[4*q+2] = v.z; yl[4*q+3] = v.w;
        }
        #pragma unroll
        for (int rs = 0; rs < 2; rs++)
            #pragma unroll
            for (int h = 0; h < 2; h++) {
                float2* dst = reinterpret_cast<float2*>(
                    out + (size_t)(rowbase + rs * 16 + h * 8) * 64);
                #pragma unroll
                for (int t = 0; t < 8; t++)
                    dst[4 * t + tig] = make_float2(yl[rs*32 + 4*t + 2*h],
                                                   yl[rs*32 + 4*t + 2*h + 1]);
            }
    }
}

extern "C" void kernel_launch(void* const* d_in, const int* in_sizes, int n_in,
                              void* d_out, int out_size) {
    const float* x  = (const float*)d_in[0];
    const float* t  = (const float*)d_in[1];
    const float* W1 = (const float*)d_in[2];
    const float* b1 = (const float*)d_in[3];
    const float* W2 = (const float*)d_in[4];
    const float* b2 = (const float*)d_in[5];
    float* out = (float*)d_out;

    cudaFuncSetAttribute(node_rk4_kernel,
                         cudaFuncAttributeMaxDynamicSharedMemorySize, SMEM_BYTES);
    node_rk4_kernel<<<NTILES, NTHREADS, SMEM_BYTES>>>(x, t, W1, b1, W2, b2, out);
}

// round 13
// speedup vs baseline: 1.0655x; 1.0524x over previous
#include <cuda_runtime.h>
#include <cuda_fp16.h>
#include <cstdint>

#define NSTEPS   64
#define NTHREADS 256
#define NTILES   1024            // 262144 rows / 256 per CTA (M=32 per warp)

// SMEM: W1 [256n][64k] half (pre-scaled by log2e), rows padded to 144B
//       W2 [64n][256k] half, rows 528B; b1 pair table (h2, pre-scaled) 512B
//       b2adj f32[64]; y state: per-thread 64 f32, 272B pitch
#define OFF_W1 0u                // 36864
#define OFF_W2 36864u            // 33792
#define OFF_B1 70656u            // 128 h2 = 512B
#define OFF_B2A 71168u           // 64 f32 = 256B
#define OFF_Y  71680u            // 256*272 = 69632
#define YPITCH 272u
#define SMEM_BYTES (OFF_Y + 256u * YPITCH)   // 141312

#define L2E 1.44269504f
#define LN2 0.69314718f

static __device__ __forceinline__ uint32_t smem_u32(const void* p) {
    uint32_t a;
    asm("{ .reg .u64 t; cvta.to.shared.u64 t, %1; cvt.u32.u64 %0, t; }" : "=r"(a) : "l"(p));
    return a;
}
static __device__ __forceinline__ void ldsm4(uint32_t* r, uint32_t addr) {
    asm volatile("ldmatrix.sync.aligned.m8n8.x4.shared.b16 {%0,%1,%2,%3}, [%4];"
                 : "=r"(r[0]), "=r"(r[1]), "=r"(r[2]), "=r"(r[3]) : "r"(addr));
}
// f16-accum MMA: D/C packed half2, 2 regs
static __device__ __forceinline__ void mma16816h(uint32_t* d, const uint32_t* a,
                                                 uint32_t b0, uint32_t b1) {
    asm volatile(
        "mma.sync.aligned.m16n8k16.row.col.f16.f16.f16.f16 "
        "{%0,%1}, {%2,%3,%4,%5}, {%6,%7}, {%0,%1};"
        : "+r"(d[0]), "+r"(d[1])
        : "r"(a[0]), "r"(a[1]), "r"(a[2]), "r"(a[3]), "r"(b0), "r"(b1));
}
static __device__ __forceinline__ uint32_t pack_h2(float a, float b) {
    __half2 h = __floats2half2_rn(a, b);
    return *reinterpret_cast<const uint32_t*>(&h);
}
static __device__ __forceinline__ __half2 exp2h2(__half2 v) {
    uint32_t r, x = *reinterpret_cast<const uint32_t*>(&v);
    asm("ex2.approx.f16x2 %0, %1;" : "=r"(r) : "r"(x));
    return *reinterpret_cast<const __half2*>(&r);
}
// 4-op fused (ELU+1) on d = log2e*h (packed h2):
//   elu(h)+1 = ex2(min(d,0)) + ln2*max(d,0)
static __device__ __forceinline__ uint32_t elup1_h2(uint32_t du) {
    const __half2 z     = __float2half2_rn(0.0f);
    const __half2 ln2_h = __float2half2_rn(LN2);
    __half2 d  = *reinterpret_cast<const __half2*>(&du);
    __half2 mn = __hmin2(d, z);
    __half2 mx = __hmax2(d, z);
    __half2 e  = exp2h2(mn);
    __half2 r  = __hfma2(mx, ln2_h, e);
    return *reinterpret_cast<const uint32_t*>(&r);
}
static __device__ __forceinline__ uint32_t hfma2_u(uint32_t a, __half2 b, uint32_t c) {
    __half2 r = __hfma2(*reinterpret_cast<const __half2*>(&a), b,
                        *reinterpret_cast<const __half2*>(&c));
    return *reinterpret_cast<const uint32_t*>(&r);
}

__global__ void __launch_bounds__(NTHREADS, 1)
node_rk4_kernel(const float* __restrict__ x, const float* __restrict__ tptr,
                const float* __restrict__ W1, const float* __restrict__ b1,
                const float* __restrict__ W2, const float* __restrict__ b2,
                float* __restrict__ out)
{
    extern __shared__ char base[];
    const int tid = threadIdx.x;
    const int wid = tid >> 5;
    const int lid = tid & 31;
    const int g   = lid >> 2;
    const int tig = lid & 3;

    // ---- stage weights (fp16, padded rows; W1/b1 pre-scaled by log2e) ----
    for (int i = tid; i < 256 * 64; i += NTHREADS) {
        int n = i >> 6, k = i & 63;
        *reinterpret_cast<__half*>(base + OFF_W1 + n * 144 + k * 2) =
            __float2half_rn(W1[i] * L2E);
    }
    for (int i = tid; i < 64 * 256; i += NTHREADS) {
        int n = i >> 8, k = i & 255;
        *reinterpret_cast<__half*>(base + OFF_W2 + n * 528 + k * 2) = __float2half_rn(W2[i]);
    }
    for (int i = tid; i < 128; i += NTHREADS) {
        int t = i >> 2, tg = i & 3;
        *reinterpret_cast<uint32_t*>(base + OFF_B1 + (uint32_t)(tg * 32 + t) * 4) =
            pack_h2(b1[8*t + 2*tg] * L2E, b1[8*t + 2*tg + 1] * L2E);
    }
    // b2adj[n] = b2[n] - sum_k W2[n,k]  (absorbs the "-1" of ELU into the bias)
    if (tid < 64) {
        float s = 0.0f;
        const float* wr = W2 + tid * 256;
        #pragma unroll 4
        for (int k = 0; k < 256; k++) s += wr[k];
        reinterpret_cast<float*>(base + OFF_B2A)[tid] = b2[tid] - s;
    }

    const uint32_t sb = smem_u32(base);
    const uint32_t lr = lid & 7, lh = (lid >> 3) & 1, ln = (lid >> 4) & 1;
    const uint32_t w1base = sb + OFF_W1 + (lr + 8 * ln) * 144 + lh * 16;
    const uint32_t w2base = sb + OFF_W2 + (lr + 8 * ln) * 528 + lh * 16;
    float* yp = reinterpret_cast<float*>(base + OFF_Y + (uint32_t)tid * YPITCH);

    const float t0f = tptr[0];
    const float dt  = t0f * (1.0f / (float)NSTEPS);
    const float dt6 = dt * (1.0f / 6.0f);
    const float hdt = 0.5f * dt;
    const __half2 one_h  = __float2half2_rn(1.0f);
    const __half2 two_h  = __float2half2_rn(2.0f);
    const __half2 hdt_h  = __float2half2_rn(hdt);
    const __half2 dt_h   = __float2half2_rn(dt);
    const int rot = ((wid >> 2) & 1) * 2;   // SMSP phase stagger

    // ---- initial y: gather C-layout slices from global x ----
    const int rowbase = blockIdx.x * 256 + wid * 32 + g;
    uint32_t a1[32];   // GEMM1 A-frags (current stage input), h2
    uint32_t yh[32];   // h2 snapshot of y (stage-0 input)
    {
        float yl[64];
        #pragma unroll
        for (int rs = 0; rs < 2; rs++)
            #pragma unroll
            for (int h = 0; h < 2; h++) {
                const float2* src = reinterpret_cast<const float2*>(
                    x + (size_t)(rowbase + rs * 16 + h * 8) * 64);
                #pragma unroll
                for (int t = 0; t < 8; t++) {
                    float2 v = src[4 * t + tig];
                    yl[rs*32 + 4*t + 2*h]     = v.x;
                    yl[rs*32 + 4*t + 2*h + 1] = v.y;
                }
            }
        #pragma unroll
        for (int q = 0; q < 16; q++)
            reinterpret_cast<float4*>(yp)[q] =
                make_float4(yl[4*q], yl[4*q+1], yl[4*q+2], yl[4*q+3]);
        #pragma unroll
        for (int i = 0; i < 32; i++) {
            a1[i] = pack_h2(yl[2*i], yl[2*i+1]);
            yh[i] = a1[i];
        }
    }
    __syncthreads();

    // b2' as h2 pairs for this thread's columns (from smem b2adj)
    uint32_t b2h[8];
    {
        const float* b2a = reinterpret_cast<const float*>(base + OFF_B2A);
        #pragma unroll
        for (int t = 0; t < 8; t++)
            b2h[t] = pack_h2(b2a[8*t + 2*tig], b2a[8*t + 2*tig + 1]);
    }

    // ---- main ODE loop ----
    #pragma unroll 1
    for (int step = 0; step < NSTEPS; ++step) {
        uint32_t acc[32];                    // RK4 accumulator (h2)
        #pragma unroll
        for (int i = 0; i < 32; i++) acc[i] = 0u;

        #pragma unroll 1
        for (int s = 0; s < 4; s++) {
            // D2 accumulators (h2), init = b2'
            uint32_t d2h[32];
            #pragma unroll
            for (int rs = 0; rs < 2; rs++)
                #pragma unroll
                for (int t = 0; t < 8; t++) {
                    d2h[rs*16 + 2*t + 0] = b2h[t];
                    d2h[rs*16 + 2*t + 1] = b2h[t];
                }

            // hidden chunks of 64 (rotated order per warp-group)
            #pragma unroll 1
            for (int hc = 0; hc < 4; hc++) {
                const int ci = (hc + rot) & 3;

                // prefetch first GEMM1 B-tile of this chunk (ngl=0, kk=0)
                uint32_t bbX[4], bbY[4];
                ldsm4(bbX, w1base + (uint32_t)(4*ci) * 2304);

                // d1h init = (scaled) b1 pairs of this chunk
                uint32_t d1h[32];
                {
                    const uint32_t boff = sb + OFF_B1 + (uint32_t)(tig * 32 + 8 * ci) * 4;
                    uint4 pA, pB;
                    asm volatile("ld.shared.v4.u32 {%0,%1,%2,%3}, [%4];"
                                 : "=r"(pA.x), "=r"(pA.y), "=r"(pA.z), "=r"(pA.w) : "r"(boff));
                    asm volatile("ld.shared.v4.u32 {%0,%1,%2,%3}, [%4];"
                                 : "=r"(pB.x), "=r"(pB.y), "=r"(pB.z), "=r"(pB.w) : "r"(boff + 16));
                    uint32_t pv[8] = {pA.x, pA.y, pA.z, pA.w, pB.x, pB.y, pB.z, pB.w};
                    #pragma unroll
                    for (int rs = 0; rs < 2; rs++)
                        #pragma unroll
                        for (int lt = 0; lt < 8; lt++) {
                            d1h[rs*16 + 2*lt + 0] = pv[lt];
                            d1h[rs*16 + 2*lt + 1] = pv[lt];
                        }
                }

                // GEMM1 chunk (f16 accum), ldsm double-buffered; kk outer, ngl inner
                #pragma unroll
                for (int j = 0; j < 16; j++) {
                    const int ngl = j & 3, kk = j >> 2;
                    uint32_t* cur = (j & 1) ? bbY : bbX;
                    uint32_t* nxt = (j & 1) ? bbX : bbY;
                    if (j < 15) {
                        const int jn = j + 1;
                        ldsm4(nxt, w1base + (uint32_t)(4*ci + (jn & 3)) * 2304 + (jn >> 2) * 32);
                    }
                    mma16816h(d1h + 4*ngl,          a1 + 4*kk,      cur[0], cur[1]);
                    mma16816h(d1h + 4*ngl + 2,      a1 + 4*kk,      cur[2], cur[3]);
                    mma16816h(d1h + 16 + 4*ngl,     a1 + 16 + 4*kk, cur[0], cur[1]);
                    mma16816h(d1h + 16 + 4*ngl + 2, a1 + 16 + 4*kk, cur[2], cur[3]);
                }

                // prefetch first GEMM2 B-tile BEFORE the activation block
                uint32_t cbX[4], cbY[4];
                ldsm4(cbX, w2base + (uint32_t)(4*ci) * 32);

                // (ELU+1): 4-op elementwise h2 (output = GEMM2 A-frags)
                uint32_t a2c[32];
                #pragma unroll
                for (int i = 0; i < 32; i++) a2c[i] = elup1_h2(d1h[i]);

                // GEMM2 partial over this k64 chunk (f16 accum), double-buffered
                #pragma unroll
                for (int j = 0; j < 16; j++) {
                    const int ng2 = j & 3, kk2 = j >> 2;
                    uint32_t* cur = (j & 1) ? cbY : cbX;
                    uint32_t* nxt = (j & 1) ? cbX : cbY;
                    if (j < 15) {
                        const int jn = j + 1;
                        ldsm4(nxt, w2base + (uint32_t)(jn & 3) * 8448
                                          + (uint32_t)(4*ci + (jn >> 2)) * 32);
                    }
                    mma16816h(d2h + 4*ng2,          a2c + 4*kk2,      cur[0], cur[1]);
                    mma16816h(d2h + 4*ng2 + 2,      a2c + 4*kk2,      cur[2], cur[3]);
                    mma16816h(d2h + 16 + 4*ng2,     a2c + 16 + 4*kk2, cur[0], cur[1]);
                    mma16816h(d2h + 16 + 4*ng2 + 2, a2c + 16 + 4*kk2, cur[2], cur[3]);
                }
            }

            // ---- RK4 stage update (all h2); a1 (gating value) first ----
            if (s < 3) {
                const __half2 cnh = (s < 2) ? hdt_h : dt_h;
                #pragma unroll
                for (int i = 0; i < 32; i++) a1[i] = hfma2_u(d2h[i], cnh, yh[i]);
                const __half2 wh = (s == 1 || s == 2) ? two_h : one_h;
                #pragma unroll
                for (int i = 0; i < 32; i++) acc[i] = hfma2_u(d2h[i], wh, acc[i]);
            } else {
                #pragma unroll
                for (int i = 0; i < 32; i++) acc[i] = hfma2_u(d2h[i], one_h, acc[i]);
                float yl[64];
                #pragma unroll
                for (int q = 0; q < 16; q++) {
                    float4 v = reinterpret_cast<const float4*>(yp)[q];
                    yl[4*q] = v.x; yl[4*q+1] = v.y; yl[4*q+2] = v.z; yl[4*q+3] = v.w;
                }
                #pragma unroll
                for (int i = 0; i < 32; i++) {
                    float2 af = __half22float2(*reinterpret_cast<const __half2*>(&acc[i]));
                    yl[2*i]     += dt6 * af.x;
                    yl[2*i + 1] += dt6 * af.y;
                }
                #pragma unroll
                for (int q = 0; q < 16; q++)
                    reinterpret_cast<float4*>(yp)[q] =
                        make_float4(yl[4*q], yl[4*q+1], yl[4*q+2], yl[4*q+3]);
                #pragma unroll
                for (int i = 0; i < 32; i++) {
                    a1[i] = pack_h2(yl[2*i], yl[2*i+1]);
                    yh[i] = a1[i];
                }
            }
        }
    }

    // ---- output ----
    {
        float yl[64];
        #pragma unroll
        for (int q = 0; q < 16; q++) {
            float4 v = reinterpret_cast<const float4*>(yp)[q];
            yl[4*q] = v.x; yl[4*q+1] = v.y; yl[4*q+2] = v.z; yl[4*q+3] = v.w;
        }
        #pragma unroll
        for (int rs = 0; rs < 2; rs++)
            #pragma unroll
            for (int h = 0; h < 2; h++) {
                float2* dst = reinterpret_cast<float2*>(
                    out + (size_t)(rowbase + rs * 16 + h * 8) * 64);
                #pragma unroll
                for (int t = 0; t < 8; t++)
                    dst[4 * t + tig] = make_float2(yl[rs*32 + 4*t + 2*h],
                                                   yl[rs*32 + 4*t + 2*h + 1]);
            }
    }
}

extern "C" void kernel_launch(void* const* d_in, const int* in_sizes, int n_in,
                              void* d_out, int out_size) {
    const float* x  = (const float*)d_in[0];
    const float* t  = (const float*)d_in[1];
    const float* W1 = (const float*)d_in[2];
    const float* b1 = (const float*)d_in[3];
    const float* W2 = (const float*)d_in[4];
    const float* b2 = (const float*)d_in[5];
    float* out = (float*)d_out;

    cudaFuncSetAttribute(node_rk4_kernel,
                         cudaFuncAttributeMaxDynamicSharedMemorySize, SMEM_BYTES);
    node_rk4_kernel<<<NTILES, NTHREADS, SMEM_BYTES>>>(x, t, W1, b1, W2, b2, out);
}

// round 14
// speedup vs baseline: 1.0748x; 1.0087x over previous
#include <cuda_runtime.h>
#include <cuda_fp16.h>
#include <cstdint>

#define NSTEPS   64
#define NTHREADS 256
#define NTILES   1024            // 262144 rows / 256 per CTA (M=32 per warp)

// SMEM: W1 [256n][64k] half (pre-scaled by log2e), rows padded to 144B
//       W2 [64n][256k] half, rows 528B; b1 pair table (h2, pre-scaled) 512B
//       b2adj f32[64]; y state: per-thread 64 f32, 272B pitch
#define OFF_W1 0u                // 36864
#define OFF_W2 36864u            // 33792
#define OFF_B1 70656u            // 128 h2 = 512B
#define OFF_B2A 71168u           // 64 f32 = 256B
#define OFF_Y  71680u            // 256*272 = 69632
#define YPITCH 272u
#define SMEM_BYTES (OFF_Y + 256u * YPITCH)   // 141312

#define L2E 1.44269504f
#define LN2 0.69314718f

static __device__ __forceinline__ uint32_t smem_u32(const void* p) {
    uint32_t a;
    asm("{ .reg .u64 t; cvta.to.shared.u64 t, %1; cvt.u32.u64 %0, t; }" : "=r"(a) : "l"(p));
    return a;
}
static __device__ __forceinline__ void ldsm4(uint32_t* r, uint32_t addr) {
    asm volatile("ldmatrix.sync.aligned.m8n8.x4.shared.b16 {%0,%1,%2,%3}, [%4];"
                 : "=r"(r[0]), "=r"(r[1]), "=r"(r[2]), "=r"(r[3]) : "r"(addr));
}
// f16-accum MMA, D += A*B (C == D)
static __device__ __forceinline__ void mma16816h(uint32_t* d, const uint32_t* a,
                                                 uint32_t b0, uint32_t b1) {
    asm volatile(
        "mma.sync.aligned.m16n8k16.row.col.f16.f16.f16.f16 "
        "{%0,%1}, {%2,%3,%4,%5}, {%6,%7}, {%0,%1};"
        : "+r"(d[0]), "+r"(d[1])
        : "r"(a[0]), "r"(a[1]), "r"(a[2]), "r"(a[3]), "r"(b0), "r"(b1));
}
// f16-accum MMA, D = A*B + C (separate C: fuses the bias init, no movs)
static __device__ __forceinline__ void mma16816h_c(uint32_t* d, const uint32_t* a,
                                                   uint32_t b0, uint32_t b1,
                                                   uint32_t c0, uint32_t c1) {
    asm volatile(
        "mma.sync.aligned.m16n8k16.row.col.f16.f16.f16.f16 "
        "{%0,%1}, {%2,%3,%4,%5}, {%6,%7}, {%8,%9};"
        : "=r"(d[0]), "=r"(d[1])
        : "r"(a[0]), "r"(a[1]), "r"(a[2]), "r"(a[3]), "r"(b0), "r"(b1),
          "r"(c0), "r"(c1));
}
static __device__ __forceinline__ uint32_t pack_h2(float a, float b) {
    __half2 h = __floats2half2_rn(a, b);
    return *reinterpret_cast<const uint32_t*>(&h);
}
static __device__ __forceinline__ __half2 exp2h2(__half2 v) {
    uint32_t r, x = *reinterpret_cast<const uint32_t*>(&v);
    asm("ex2.approx.f16x2 %0, %1;" : "=r"(r) : "r"(x));
    return *reinterpret_cast<const __half2*>(&r);
}
// 4-op fused (ELU+1) on d = log2e*h (packed h2):
//   elu(h)+1 = ex2(min(d,0)) + ln2*max(d,0)
static __device__ __forceinline__ uint32_t elup1_h2(uint32_t du) {
    const __half2 z     = __float2half2_rn(0.0f);
    const __half2 ln2_h = __float2half2_rn(LN2);
    __half2 d  = *reinterpret_cast<const __half2*>(&du);
    __half2 mn = __hmin2(d, z);
    __half2 mx = __hmax2(d, z);
    __half2 e  = exp2h2(mn);
    __half2 r  = __hfma2(mx, ln2_h, e);
    return *reinterpret_cast<const uint32_t*>(&r);
}
static __device__ __forceinline__ uint32_t hfma2_u(uint32_t a, __half2 b, uint32_t c) {
    __half2 r = __hfma2(*reinterpret_cast<const __half2*>(&a), b,
                        *reinterpret_cast<const __half2*>(&c));
    return *reinterpret_cast<const uint32_t*>(&r);
}

// One hidden-chunk (64 cols): GEMM1 (bias fused via C operand) -> ELU+1 -> GEMM2.
// FIRST: this is the first chunk visited in the stage -> GEMM2 kk2=0 uses
// C = b2' (fused init); otherwise GEMM2 accumulates into d2h.
template<bool FIRST>
static __device__ __forceinline__ void run_chunk(
    int ci, uint32_t sb, uint32_t w1base, uint32_t w2base, int tig,
    const uint32_t* __restrict__ a1, const uint32_t* __restrict__ b2h,
    uint32_t* __restrict__ d2h)
{
    // prefetch first GEMM1 B-tile of this chunk (ngl=0, kk=0)
    uint32_t bbX[4], bbY[4];
    ldsm4(bbX, w1base + (uint32_t)(4*ci) * 2304);

    // (scaled) b1 pairs of this chunk
    uint32_t pv[8];
    {
        const uint32_t boff = sb + OFF_B1 + (uint32_t)(tig * 32 + 8 * ci) * 4;
        asm volatile("ld.shared.v4.u32 {%0,%1,%2,%3}, [%4];"
                     : "=r"(pv[0]), "=r"(pv[1]), "=r"(pv[2]), "=r"(pv[3]) : "r"(boff));
        asm volatile("ld.shared.v4.u32 {%0,%1,%2,%3}, [%4];"
                     : "=r"(pv[4]), "=r"(pv[5]), "=r"(pv[6]), "=r"(pv[7]) : "r"(boff + 16));
    }

    uint32_t d1h[32];

    // GEMM1 chunk (f16 accum), ldsm double-buffered; kk outer, ngl inner.
    // kk==0 initializes accumulators via the C operand (b1 pairs) -> no movs.
    #pragma unroll
    for (int j = 0; j < 16; j++) {
        const int ngl = j & 3, kk = j >> 2;
        uint32_t* cur = (j & 1) ? bbY : bbX;
        uint32_t* nxt = (j & 1) ? bbX : bbY;
        if (j < 15) {
            const int jn = j + 1;
            ldsm4(nxt, w1base + (uint32_t)(4*ci + (jn & 3)) * 2304 + (jn >> 2) * 32);
        }
        if (kk == 0) {
            mma16816h_c(d1h + 4*ngl,          a1,      cur[0], cur[1], pv[2*ngl],   pv[2*ngl]);
            mma16816h_c(d1h + 4*ngl + 2,      a1,      cur[2], cur[3], pv[2*ngl+1], pv[2*ngl+1]);
            mma16816h_c(d1h + 16 + 4*ngl,     a1 + 16, cur[0], cur[1], pv[2*ngl],   pv[2*ngl]);
            mma16816h_c(d1h + 16 + 4*ngl + 2, a1 + 16, cur[2], cur[3], pv[2*ngl+1], pv[2*ngl+1]);
        } else {
            mma16816h(d1h + 4*ngl,          a1 + 4*kk,      cur[0], cur[1]);
            mma16816h(d1h + 4*ngl + 2,      a1 + 4*kk,      cur[2], cur[3]);
            mma16816h(d1h + 16 + 4*ngl,     a1 + 16 + 4*kk, cur[0], cur[1]);
            mma16816h(d1h + 16 + 4*ngl + 2, a1 + 16 + 4*kk, cur[2], cur[3]);
        }
    }

    // prefetch first GEMM2 B-tile BEFORE the activation block
    uint32_t cbX[4], cbY[4];
    ldsm4(cbX, w2base + (uint32_t)(4*ci) * 32);

    // (ELU+1): 4-op elementwise h2 (output = GEMM2 A-frags)
    uint32_t a2c[32];
    #pragma unroll
    for (int i = 0; i < 32; i++) a2c[i] = elup1_h2(d1h[i]);

    // GEMM2 partial over this k64 chunk (f16 accum), double-buffered.
    // On the FIRST chunk, kk2==0 initializes d2h via C = b2' -> no movs.
    #pragma unroll
    for (int j = 0; j < 16; j++) {
        const int ng2 = j & 3, kk2 = j >> 2;
        uint32_t* cur = (j & 1) ? cbY : cbX;
        uint32_t* nxt = (j & 1) ? cbX : cbY;
        if (j < 15) {
            const int jn = j + 1;
            ldsm4(nxt, w2base + (uint32_t)(jn & 3) * 8448
                              + (uint32_t)(4*ci + (jn >> 2)) * 32);
        }
        if (FIRST && kk2 == 0) {
            mma16816h_c(d2h + 4*ng2,          a2c,      cur[0], cur[1], b2h[2*ng2],   b2h[2*ng2]);
            mma16816h_c(d2h + 4*ng2 + 2,      a2c,      cur[2], cur[3], b2h[2*ng2+1], b2h[2*ng2+1]);
            mma16816h_c(d2h + 16 + 4*ng2,     a2c + 16, cur[0], cur[1], b2h[2*ng2],   b2h[2*ng2]);
            mma16816h_c(d2h + 16 + 4*ng2 + 2, a2c + 16, cur[2], cur[3], b2h[2*ng2+1], b2h[2*ng2+1]);
        } else {
            mma16816h(d2h + 4*ng2,          a2c + 4*kk2,      cur[0], cur[1]);
            mma16816h(d2h + 4*ng2 + 2,      a2c + 4*kk2,      cur[2], cur[3]);
            mma16816h(d2h + 16 + 4*ng2,     a2c + 16 + 4*kk2, cur[0], cur[1]);
            mma16816h(d2h + 16 + 4*ng2 + 2, a2c + 16 + 4*kk2, cur[2], cur[3]);
        }
    }
}

__global__ void __launch_bounds__(NTHREADS, 1)
node_rk4_kernel(const float* __restrict__ x, const float* __restrict__ tptr,
                const float* __restrict__ W1, const float* __restrict__ b1,
                const float* __restrict__ W2, const float* __restrict__ b2,
                float* __restrict__ out)
{
    extern __shared__ char base[];
    const int tid = threadIdx.x;
    const int wid = tid >> 5;
    const int lid = tid & 31;
    const int g   = lid >> 2;
    const int tig = lid & 3;

    // ---- stage weights (fp16, padded rows; W1/b1 pre-scaled by log2e) ----
    for (int i = tid; i < 256 * 64; i += NTHREADS) {
        int n = i >> 6, k = i & 63;
        *reinterpret_cast<__half*>(base + OFF_W1 + n * 144 + k * 2) =
            __float2half_rn(W1[i] * L2E);
    }
    for (int i = tid; i < 64 * 256; i += NTHREADS) {
        int n = i >> 8, k = i & 255;
        *reinterpret_cast<__half*>(base + OFF_W2 + n * 528 + k * 2) = __float2half_rn(W2[i]);
    }
    for (int i = tid; i < 128; i += NTHREADS) {
        int t = i >> 2, tg = i & 3;
        *reinterpret_cast<uint32_t*>(base + OFF_B1 + (uint32_t)(tg * 32 + t) * 4) =
            pack_h2(b1[8*t + 2*tg] * L2E, b1[8*t + 2*tg + 1] * L2E);
    }
    // b2adj[n] = b2[n] - sum_k W2[n,k]  (absorbs the "-1" of ELU into the bias)
    if (tid < 64) {
        float s = 0.0f;
        const float* wr = W2 + tid * 256;
        #pragma unroll 4
        for (int k = 0; k < 256; k++) s += wr[k];
        reinterpret_cast<float*>(base + OFF_B2A)[tid] = b2[tid] - s;
    }

    const uint32_t sb = smem_u32(base);
    const uint32_t lr = lid & 7, lh = (lid >> 3) & 1, ln = (lid >> 4) & 1;
    const uint32_t w1base = sb + OFF_W1 + (lr + 8 * ln) * 144 + lh * 16;
    const uint32_t w2base = sb + OFF_W2 + (lr + 8 * ln) * 528 + lh * 16;
    float* yp = reinterpret_cast<float*>(base + OFF_Y + (uint32_t)tid * YPITCH);

    const float t0f = tptr[0];
    const float dt  = t0f * (1.0f / (float)NSTEPS);
    const float dt6 = dt * (1.0f / 6.0f);
    const float hdt = 0.5f * dt;
    const __half2 one_h  = __float2half2_rn(1.0f);
    const __half2 two_h  = __float2half2_rn(2.0f);
    const __half2 hdt_h  = __float2half2_rn(hdt);
    const __half2 dt_h   = __float2half2_rn(dt);
    const int rot = ((wid >> 2) & 1) * 2;   // SMSP phase stagger

    // ---- initial y: gather C-layout slices from global x ----
    const int rowbase = blockIdx.x * 256 + wid * 32 + g;
    uint32_t a1[32];   // GEMM1 A-frags (current stage input), h2
    uint32_t yh[32];   // h2 snapshot of y (stage-0 input)
    {
        float yl[64];
        #pragma unroll
        for (int rs = 0; rs < 2; rs++)
            #pragma unroll
            for (int h = 0; h < 2; h++) {
                const float2* src = reinterpret_cast<const float2*>(
                    x + (size_t)(rowbase + rs * 16 + h * 8) * 64);
                #pragma unroll
                for (int t = 0; t < 8; t++) {
                    float2 v = src[4 * t + tig];
                    yl[rs*32 + 4*t + 2*h]     = v.x;
                    yl[rs*32 + 4*t + 2*h + 1] = v.y;
                }
            }
        #pragma unroll
        for (int q = 0; q < 16; q++)
            reinterpret_cast<float4*>(yp)[q] =
                make_float4(yl[4*q], yl[4*q+1], yl[4*q+2], yl[4*q+3]);
        #pragma unroll
        for (int i = 0; i < 32; i++) {
            a1[i] = pack_h2(yl[2*i], yl[2*i+1]);
            yh[i] = a1[i];
        }
    }
    __syncthreads();

    // b2' as h2 pairs for this thread's columns (from smem b2adj)
    uint32_t b2h[8];
    {
        const float* b2a = reinterpret_cast<const float*>(base + OFF_B2A);
        #pragma unroll
        for (int t = 0; t < 8; t++)
            b2h[t] = pack_h2(b2a[8*t + 2*tig], b2a[8*t + 2*tig + 1]);
    }

    // ---- main ODE loop ----
    #pragma unroll 1
    for (int step = 0; step < NSTEPS; ++step) {
        uint32_t acc[32];                    // RK4 accumulator (h2)
        #pragma unroll
        for (int i = 0; i < 32; i++) acc[i] = 0u;

        #pragma unroll 1
        for (int s = 0; s < 4; s++) {
            uint32_t d2h[32];                // initialized by first chunk's C-fused MMAs

            run_chunk<true>(rot, sb, w1base, w2base, tig, a1, b2h, d2h);
            #pragma unroll 1
            for (int hc = 1; hc < 4; hc++)
                run_chunk<false>((hc + rot) & 3, sb, w1base, w2base, tig, a1, b2h, d2h);

            // ---- RK4 stage update (all h2); a1 (gating value) first ----
            if (s < 3) {
                const __half2 cnh = (s < 2) ? hdt_h : dt_h;
                #pragma unroll
                for (int i = 0; i < 32; i++) a1[i] = hfma2_u(d2h[i], cnh, yh[i]);
                const __half2 wh = (s == 1 || s == 2) ? two_h : one_h;
                #pragma unroll
                for (int i = 0; i < 32; i++) acc[i] = hfma2_u(d2h[i], wh, acc[i]);
            } else {
                #pragma unroll
                for (int i = 0; i < 32; i++) acc[i] = hfma2_u(d2h[i], one_h, acc[i]);
                float yl[64];
                #pragma unroll
                for (int q = 0; q < 16; q++) {
                    float4 v = reinterpret_cast<const float4*>(yp)[q];
                    yl[4*q] = v.x; yl[4*q+1] = v.y; yl[4*q+2] = v.z; yl[4*q+3] = v.w;
                }
                #pragma unroll
                for (int i = 0; i < 32; i++) {
                    float2 af = __half22float2(*reinterpret_cast<const __half2*>(&acc[i]));
                    yl[2*i]     += dt6 * af.x;
                    yl[2*i + 1] += dt6 * af.y;
                }
                #pragma unroll
                for (int q = 0; q < 16; q++)
                    reinterpret_cast<float4*>(yp)[q] =
                        make_float4(yl[4*q], yl[4*q+1], yl[4*q+2], yl[4*q+3]);
                #pragma unroll
                for (int i = 0; i < 32; i++) {
                    a1[i] = pack_h2(yl[2*i], yl[2*i+1]);
                    yh[i] = a1[i];
                }
            }
        }
    }

    // ---- output ----
    {
        float yl[64];
        #pragma unroll
        for (int q = 0; q < 16; q++) {
            float4 v = reinterpret_cast<const float4*>(yp)[q];
            yl[4*q] = v.x; yl[4*q+1] = v.y; yl[4*q+2] = v.z; yl[4*q+3] = v.w;
        }
        #pragma unroll
        for (int rs = 0; rs < 2; rs++)
            #pragma unroll
            for (int h = 0; h < 2; h++) {
                float2* dst = reinterpret_cast<float2*>(
                    out + (size_t)(rowbase + rs * 16 + h * 8) * 64);
                #pragma unroll
                for (int t = 0; t < 8; t++)
                    dst[4 * t + tig] = make_float2(yl[rs*32 + 4*t + 2*h],
                                                   yl[rs*32 + 4*t + 2*h + 1]);
            }
    }
}

extern "C" void kernel_launch(void* const* d_in, const int* in_sizes, int n_in,
                              void* d_out, int out_size) {
    const float* x  = (const float*)d_in[0];
    const float* t  = (const float*)d_in[1];
    const float* W1 = (const float*)d_in[2];
    const float* b1 = (const float*)d_in[3];
    const float* W2 = (const float*)d_in[4];
    const float* b2 = (const float*)d_in[5];
    float* out = (float*)d_out;

    cudaFuncSetAttribute(node_rk4_kernel,
                         cudaFuncAttributeMaxDynamicSharedMemorySize, SMEM_BYTES);
    node_rk4_kernel<<<NTILES, NTHREADS, SMEM_BYTES>>>(x, t, W1, b1, W2, b2, out);
}

// round 15
// speedup vs baseline: 1.0931x; 1.0170x over previous
#include <cuda_runtime.h>
#include <cuda_fp16.h>
#include <cstdint>

#define NSTEPS   64
#define NTHREADS 256
#define NTILES   1024            // 262144 rows / 256 per CTA (M=32 per warp)

// SMEM: W1 [256n][64k] half (pre-scaled by log2e), rows padded to 144B
//       W2 [64n][256k] half, rows 528B; b1 pair table (h2, pre-scaled) 512B
//       b2adj f32[64]; y state: per-thread 64 f32, 272B pitch
#define OFF_W1 0u                // 36864
#define OFF_W2 36864u            // 33792
#define OFF_B1 70656u            // 128 h2 = 512B
#define OFF_B2A 71168u           // 64 f32 = 256B
#define OFF_Y  71680u            // 256*272 = 69632
#define YPITCH 272u
#define SMEM_BYTES (OFF_Y + 256u * YPITCH)   // 141312

#define L2E 1.44269504f
#define LN2 0.69314718f

static __device__ __forceinline__ uint32_t smem_u32(const void* p) {
    uint32_t a;
    asm("{ .reg .u64 t; cvta.to.shared.u64 t, %1; cvt.u32.u64 %0, t; }" : "=r"(a) : "l"(p));
    return a;
}
static __device__ __forceinline__ void ldsm4(uint32_t* r, uint32_t addr) {
    asm volatile("ldmatrix.sync.aligned.m8n8.x4.shared.b16 {%0,%1,%2,%3}, [%4];"
                 : "=r"(r[0]), "=r"(r[1]), "=r"(r[2]), "=r"(r[3]) : "r"(addr));
}
// f16-accum MMA, D += A*B (C == D)
static __device__ __forceinline__ void mma16816h(uint32_t* d, const uint32_t* a,
                                                 uint32_t b0, uint32_t b1) {
    asm volatile(
        "mma.sync.aligned.m16n8k16.row.col.f16.f16.f16.f16 "
        "{%0,%1}, {%2,%3,%4,%5}, {%6,%7}, {%0,%1};"
        : "+r"(d[0]), "+r"(d[1])
        : "r"(a[0]), "r"(a[1]), "r"(a[2]), "r"(a[3]), "r"(b0), "r"(b1));
}
// f16-accum MMA, D = A*B + C (separate C: fuses the bias init, no movs)
static __device__ __forceinline__ void mma16816h_c(uint32_t* d, const uint32_t* a,
                                                   uint32_t b0, uint32_t b1,
                                                   uint32_t c0, uint32_t c1) {
    asm volatile(
        "mma.sync.aligned.m16n8k16.row.col.f16.f16.f16.f16 "
        "{%0,%1}, {%2,%3,%4,%5}, {%6,%7}, {%8,%9};"
        : "=r"(d[0]), "=r"(d[1])
        : "r"(a[0]), "r"(a[1]), "r"(a[2]), "r"(a[3]), "r"(b0), "r"(b1),
          "r"(c0), "r"(c1));
}
static __device__ __forceinline__ uint32_t pack_h2(float a, float b) {
    __half2 h = __floats2half2_rn(a, b);
    return *reinterpret_cast<const uint32_t*>(&h);
}
static __device__ __forceinline__ __half2 exp2h2(__half2 v) {
    uint32_t r, x = *reinterpret_cast<const uint32_t*>(&v);
    asm("ex2.approx.f16x2 %0, %1;" : "=r"(r) : "r"(x));
    return *reinterpret_cast<const __half2*>(&r);
}
// 4-op fused (ELU+1) on d = log2e*h (packed h2):
//   elu(h)+1 = ex2(min(d,0)) + ln2*max(d,0)
static __device__ __forceinline__ uint32_t elup1_h2(uint32_t du) {
    const __half2 z     = __float2half2_rn(0.0f);
    const __half2 ln2_h = __float2half2_rn(LN2);
    __half2 d  = *reinterpret_cast<const __half2*>(&du);
    __half2 mn = __hmin2(d, z);
    __half2 mx = __hmax2(d, z);
    __half2 e  = exp2h2(mn);
    __half2 r  = __hfma2(mx, ln2_h, e);
    return *reinterpret_cast<const uint32_t*>(&r);
}
static __device__ __forceinline__ uint32_t hfma2_u(uint32_t a, __half2 b, uint32_t c) {
    __half2 r = __hfma2(*reinterpret_cast<const __half2*>(&a), b,
                        *reinterpret_cast<const __half2*>(&c));
    return *reinterpret_cast<const uint32_t*>(&r);
}

// One hidden-chunk (64 cols): GEMM1 (bias fused via C) -> ELU+1 -> GEMM2.
// CI is a compile-time chunk index -> all smem addresses are base + immediate.
template<bool FIRST, int CI>
static __device__ __forceinline__ void run_chunk(
    uint32_t sb, uint32_t w1base, uint32_t w2base, int tig,
    const uint32_t* __restrict__ a1, const uint32_t* __restrict__ b2h,
    uint32_t* __restrict__ d2h)
{
    // prefetch first GEMM1 B-tile of this chunk (ngl=0, kk=0)
    uint32_t bbX[4], bbY[4];
    ldsm4(bbX, w1base + (uint32_t)(4*CI) * 2304);

    // (scaled) b1 pairs of this chunk
    uint32_t pv[8];
    {
        const uint32_t boff = sb + OFF_B1 + (uint32_t)(tig * 32 + 8 * CI) * 4;
        asm volatile("ld.shared.v4.u32 {%0,%1,%2,%3}, [%4];"
                     : "=r"(pv[0]), "=r"(pv[1]), "=r"(pv[2]), "=r"(pv[3]) : "r"(boff));
        asm volatile("ld.shared.v4.u32 {%0,%1,%2,%3}, [%4];"
                     : "=r"(pv[4]), "=r"(pv[5]), "=r"(pv[6]), "=r"(pv[7]) : "r"(boff + 16));
    }

    uint32_t d1h[32];

    // GEMM1 chunk (f16 accum), ldsm double-buffered; kk outer, ngl inner.
    // kk==0 initializes accumulators via the C operand (b1 pairs) -> no movs.
    #pragma unroll
    for (int j = 0; j < 16; j++) {
        const int ngl = j & 3, kk = j >> 2;
        uint32_t* cur = (j & 1) ? bbY : bbX;
        uint32_t* nxt = (j & 1) ? bbX : bbY;
        if (j < 15) {
            const int jn = j + 1;
            ldsm4(nxt, w1base + (uint32_t)(4*CI + (jn & 3)) * 2304 + (jn >> 2) * 32);
        }
        if (kk == 0) {
            mma16816h_c(d1h + 4*ngl,          a1,      cur[0], cur[1], pv[2*ngl],   pv[2*ngl]);
            mma16816h_c(d1h + 4*ngl + 2,      a1,      cur[2], cur[3], pv[2*ngl+1], pv[2*ngl+1]);
            mma16816h_c(d1h + 16 + 4*ngl,     a1 + 16, cur[0], cur[1], pv[2*ngl],   pv[2*ngl]);
            mma16816h_c(d1h + 16 + 4*ngl + 2, a1 + 16, cur[2], cur[3], pv[2*ngl+1], pv[2*ngl+1]);
        } else {
            mma16816h(d1h + 4*ngl,          a1 + 4*kk,      cur[0], cur[1]);
            mma16816h(d1h + 4*ngl + 2,      a1 + 4*kk,      cur[2], cur[3]);
            mma16816h(d1h + 16 + 4*ngl,     a1 + 16 + 4*kk, cur[0], cur[1]);
            mma16816h(d1h + 16 + 4*ngl + 2, a1 + 16 + 4*kk, cur[2], cur[3]);
        }
    }

    // prefetch first GEMM2 B-tile BEFORE the activation block
    uint32_t cbX[4], cbY[4];
    ldsm4(cbX, w2base + (uint32_t)(4*CI) * 32);

    // (ELU+1): 4-op elementwise h2 (output = GEMM2 A-frags)
    uint32_t a2c[32];
    #pragma unroll
    for (int i = 0; i < 32; i++) a2c[i] = elup1_h2(d1h[i]);

    // GEMM2 partial over this k64 chunk (f16 accum), double-buffered.
    // On the FIRST chunk, kk2==0 initializes d2h via C = b2' -> no movs.
    #pragma unroll
    for (int j = 0; j < 16; j++) {
        const int ng2 = j & 3, kk2 = j >> 2;
        uint32_t* cur = (j & 1) ? cbY : cbX;
        uint32_t* nxt = (j & 1) ? cbX : cbY;
        if (j < 15) {
            const int jn = j + 1;
            ldsm4(nxt, w2base + (uint32_t)(jn & 3) * 8448
                              + (uint32_t)(4*CI + (jn >> 2)) * 32);
        }
        if (FIRST && kk2 == 0) {
            mma16816h_c(d2h + 4*ng2,          a2c,      cur[0], cur[1], b2h[2*ng2],   b2h[2*ng2]);
            mma16816h_c(d2h + 4*ng2 + 2,      a2c,      cur[2], cur[3], b2h[2*ng2+1], b2h[2*ng2+1]);
            mma16816h_c(d2h + 16 + 4*ng2,     a2c + 16, cur[0], cur[1], b2h[2*ng2],   b2h[2*ng2]);
            mma16816h_c(d2h + 16 + 4*ng2 + 2, a2c + 16, cur[2], cur[3], b2h[2*ng2+1], b2h[2*ng2+1]);
        } else {
            mma16816h(d2h + 4*ng2,          a2c + 4*kk2,      cur[0], cur[1]);
            mma16816h(d2h + 4*ng2 + 2,      a2c + 4*kk2,      cur[2], cur[3]);
            mma16816h(d2h + 16 + 4*ng2,     a2c + 16 + 4*kk2, cur[0], cur[1]);
            mma16816h(d2h + 16 + 4*ng2 + 2, a2c + 16 + 4*kk2, cur[2], cur[3]);
        }
    }
}

__global__ void __launch_bounds__(NTHREADS, 1)
node_rk4_kernel(const float* __restrict__ x, const float* __restrict__ tptr,
                const float* __restrict__ W1, const float* __restrict__ b1,
                const float* __restrict__ W2, const float* __restrict__ b2,
                float* __restrict__ out)
{
    extern __shared__ char base[];
    const int tid = threadIdx.x;
    const int wid = tid >> 5;
    const int lid = tid & 31;
    const int g   = lid >> 2;
    const int tig = lid & 3;

    // ---- stage weights (fp16, padded rows; W1/b1 pre-scaled by log2e) ----
    for (int i = tid; i < 256 * 64; i += NTHREADS) {
        int n = i >> 6, k = i & 63;
        *reinterpret_cast<__half*>(base + OFF_W1 + n * 144 + k * 2) =
            __float2half_rn(W1[i] * L2E);
    }
    for (int i = tid; i < 64 * 256; i += NTHREADS) {
        int n = i >> 8, k = i & 255;
        *reinterpret_cast<__half*>(base + OFF_W2 + n * 528 + k * 2) = __float2half_rn(W2[i]);
    }
    for (int i = tid; i < 128; i += NTHREADS) {
        int t = i >> 2, tg = i & 3;
        *reinterpret_cast<uint32_t*>(base + OFF_B1 + (uint32_t)(tg * 32 + t) * 4) =
            pack_h2(b1[8*t + 2*tg] * L2E, b1[8*t + 2*tg + 1] * L2E);
    }
    // b2adj[n] = b2[n] - sum_k W2[n,k]  (absorbs the "-1" of ELU into the bias)
    if (tid < 64) {
        float s = 0.0f;
        const float* wr = W2 + tid * 256;
        #pragma unroll 4
        for (int k = 0; k < 256; k++) s += wr[k];
        reinterpret_cast<float*>(base + OFF_B2A)[tid] = b2[tid] - s;
    }

    const uint32_t sb = smem_u32(base);
    const uint32_t lr = lid & 7, lh = (lid >> 3) & 1, ln = (lid >> 4) & 1;
    const uint32_t w1base = sb + OFF_W1 + (lr + 8 * ln) * 144 + lh * 16;
    const uint32_t w2base = sb + OFF_W2 + (lr + 8 * ln) * 528 + lh * 16;
    float* yp = reinterpret_cast<float*>(base + OFF_Y + (uint32_t)tid * YPITCH);

    const float t0f = tptr[0];
    const float dt  = t0f * (1.0f / (float)NSTEPS);
    const float dt6 = dt * (1.0f / 6.0f);
    const float hdt = 0.5f * dt;
    const __half2 one_h  = __float2half2_rn(1.0f);
    const __half2 two_h  = __float2half2_rn(2.0f);
    const __half2 hdt_h  = __float2half2_rn(hdt);
    const __half2 dt_h   = __float2half2_rn(dt);

    // ---- initial y: gather C-layout slices from global x ----
    const int rowbase = blockIdx.x * 256 + wid * 32 + g;
    uint32_t a1[32];   // GEMM1 A-frags (current stage input), h2
    uint32_t yh[32];   // h2 snapshot of y (stage-0 input)
    {
        float yl[64];
        #pragma unroll
        for (int rs = 0; rs < 2; rs++)
            #pragma unroll
            for (int h = 0; h < 2; h++) {
                const float2* src = reinterpret_cast<const float2*>(
                    x + (size_t)(rowbase + rs * 16 + h * 8) * 64);
                #pragma unroll
                for (int t = 0; t < 8; t++) {
                    float2 v = src[4 * t + tig];
                    yl[rs*32 + 4*t + 2*h]     = v.x;
                    yl[rs*32 + 4*t + 2*h + 1] = v.y;
                }
            }
        #pragma unroll
        for (int q = 0; q < 16; q++)
            reinterpret_cast<float4*>(yp)[q] =
                make_float4(yl[4*q], yl[4*q+1], yl[4*q+2], yl[4*q+3]);
        #pragma unroll
        for (int i = 0; i < 32; i++) {
            a1[i] = pack_h2(yl[2*i], yl[2*i+1]);
            yh[i] = a1[i];
        }
    }
    __syncthreads();

    // b2' as h2 pairs for this thread's columns (from smem b2adj)
    uint32_t b2h[8];
    {
        const float* b2a = reinterpret_cast<const float*>(base + OFF_B2A);
        #pragma unroll
        for (int t = 0; t < 8; t++)
            b2h[t] = pack_h2(b2a[8*t + 2*tig], b2a[8*t + 2*tig + 1]);
    }

    // ---- main ODE loop ----
    #pragma unroll 1
    for (int step = 0; step < NSTEPS; ++step) {
        uint32_t acc[32];                    // RK4 accumulator (h2)
        #pragma unroll
        for (int i = 0; i < 32; i++) acc[i] = 0u;

        #pragma unroll 1
        for (int s = 0; s < 4; s++) {
            uint32_t d2h[32];                // initialized by first chunk's C-fused MMAs

            // fully-unrolled chunk sequence: all smem addrs are base+imm, and
            // ptxas can interleave chunk i's GEMM2 tail with chunk i+1's GEMM1
            run_chunk<true,  0>(sb, w1base, w2base, tig, a1, b2h, d2h);
            run_chunk<false, 1>(sb, w1base, w2base, tig, a1, b2h, d2h);
            run_chunk<false, 2>(sb, w1base, w2base, tig, a1, b2h, d2h);
            run_chunk<false, 3>(sb, w1base, w2base, tig, a1, b2h, d2h);

            // ---- RK4 stage update (all h2); a1 (gating value) first ----
            if (s < 3) {
                const __half2 cnh = (s < 2) ? hdt_h : dt_h;
                #pragma unroll
                for (int i = 0; i < 32; i++) a1[i] = hfma2_u(d2h[i], cnh, yh[i]);
                const __half2 wh = (s == 1 || s == 2) ? two_h : one_h;
                #pragma unroll
                for (int i = 0; i < 32; i++) acc[i] = hfma2_u(d2h[i], wh, acc[i]);
            } else {
                #pragma unroll
                for (int i = 0; i < 32; i++) acc[i] = hfma2_u(d2h[i], one_h, acc[i]);
                float yl[64];
                #pragma unroll
                for (int q = 0; q < 16; q++) {
                    float4 v = reinterpret_cast<const float4*>(yp)[q];
                    yl[4*q] = v.x; yl[4*q+1] = v.y; yl[4*q+2] = v.z; yl[4*q+3] = v.w;
                }
                #pragma unroll
                for (int i = 0; i < 32; i++) {
                    float2 af = __half22float2(*reinterpret_cast<const __half2*>(&acc[i]));
                    yl[2*i]     += dt6 * af.x;
                    yl[2*i + 1] += dt6 * af.y;
                }
                #pragma unroll
                for (int q = 0; q < 16; q++)
                    reinterpret_cast<float4*>(yp)[q] =
                        make_float4(yl[4*q], yl[4*q+1], yl[4*q+2], yl[4*q+3]);
                #pragma unroll
                for (int i = 0; i < 32; i++) {
                    a1[i] = pack_h2(yl[2*i], yl[2*i+1]);
                    yh[i] = a1[i];
                }
            }
        }
    }

    // ---- output ----
    {
        float yl[64];
        #pragma unroll
        for (int q = 0; q < 16; q++) {
            float4 v = reinterpret_cast<const float4*>(yp)[q];
            yl[4*q] = v.x; yl[4*q+1] = v.y; yl[4*q+2] = v.z; yl[4*q+3] = v.w;
        }
        #pragma unroll
        for (int rs = 0; rs < 2; rs++)
            #pragma unroll
            for (int h = 0; h < 2; h++) {
                float2* dst = reinterpret_cast<float2*>(
                    out + (size_t)(rowbase + rs * 16 + h * 8) * 64);
                #pragma unroll
                for (int t = 0; t < 8; t++)
                    dst[4 * t + tig] = make_float2(yl[rs*32 + 4*t + 2*h],
                                                   yl[rs*32 + 4*t + 2*h + 1]);
            }
    }
}

extern "C" void kernel_launch(void* const* d_in, const int* in_sizes, int n_in,
                              void* d_out, int out_size) {
    const float* x  = (const float*)d_in[0];
    const float* t  = (const float*)d_in[1];
    const float* W1 = (const float*)d_in[2];
    const float* b1 = (const float*)d_in[3];
    const float* W2 = (const float*)d_in[4];
    const float* b2 = (const float*)d_in[5];
    float* out = (float*)d_out;

    cudaFuncSetAttribute(node_rk4_kernel,
                         cudaFuncAttributeMaxDynamicSharedMemorySize, SMEM_BYTES);
    node_rk4_kernel<<<NTILES, NTHREADS, SMEM_BYTES>>>(x, t, W1, b1, W2, b2, out);
}